// round 3
// baseline (speedup 1.0000x reference)
#include <cuda_runtime.h>
#include <cuda_bf16.h>
#include <math.h>

#define BATCH 4
#define SEQ   2048
#define HDIM  128
#define HEADS 4
#define HD    32
#define RNK   8
#define FEAT  48            // 32 (qk) + 8 (u/v bias) + 8 zero pad
#define KPAD  48            // Ks row stride (elements) — conflict-free LDS.64
#define VPAD  80            // Vt row stride
#define APAD  72            // adj row stride
#define QTILE 32
#define CHUNK 64
#define NTOT  (BATCH * SEQ * HDIM)

// Permuted element layout inside every 16-element group (feature dim of Q/K,
// key dim of V^T): logical (2t+e) -> slot (4t+e); logical (8+2t+e) -> slot (4t+2+e).
// This makes each m16n8k16 B-operand (b0,b1) one contiguous 8-byte word.

// ---------------- static device scratch ------------------------------------
__device__ __align__(16) __nv_bfloat16 g_qa[BATCH * HEADS * SEQ * FEAT];
__device__ __align__(16) __nv_bfloat16 g_ka[BATCH * HEADS * SEQ * FEAT];
__device__ __align__(16) __nv_bfloat16 g_vt[BATCH * HEADS * HD * SEQ];
__device__ __align__(16) __nv_bfloat16 g_adjb[SEQ * SEQ];
__device__ __align__(16) float         g_o[BATCH * HEADS * SEQ * HD];

// ---------------- helpers ---------------------------------------------------
__device__ __forceinline__ unsigned packbf(float lo, float hi) {
    unsigned r;
    asm("cvt.rn.bf16x2.f32 %0, %1, %2;" : "=r"(r) : "f"(hi), "f"(lo));
    return r;
}
__device__ __forceinline__ float bflo(unsigned u) { return __int_as_float(u << 16); }
__device__ __forceinline__ float bfhi(unsigned u) { return __int_as_float(u & 0xffff0000u); }

// slot of logical index c within its 16-group (perm above)
__device__ __host__ __forceinline__ int perm16(int c) {
    int g = c & ~15, c16 = c & 15;
    return g + 4 * ((c16 >> 1) & 3) + 2 * (c16 >> 3) + (c16 & 1);
}

__device__ __forceinline__ void mma16816(float& c0, float& c1, float& c2, float& c3,
                                         unsigned a0, unsigned a1, unsigned a2, unsigned a3,
                                         unsigned b0, unsigned b1) {
    asm volatile("mma.sync.aligned.m16n8k16.row.col.f32.bf16.bf16.f32 "
                 "{%0,%1,%2,%3}, {%4,%5,%6,%7}, {%8,%9}, {%0,%1,%2,%3};"
                 : "+f"(c0), "+f"(c1), "+f"(c2), "+f"(c3)
                 : "r"(a0), "r"(a1), "r"(a2), "r"(a3), "r"(b0), "r"(b1));
}

__device__ __forceinline__ void cp16(unsigned smem_dst, const void* gsrc) {
    asm volatile("cp.async.cg.shared.global [%0], [%1], 16;" :: "r"(smem_dst), "l"(gsrc));
}

// =============================================================================
// Prologue 1: adj fp32 -> bf16
// =============================================================================
__global__ __launch_bounds__(256) void adjcvt_kernel(const float* __restrict__ adj) {
    int i = blockIdx.x * 256 + threadIdx.x;
    const float4* src = (const float4*)adj + (size_t)i * 2;
    float4 f0 = src[0], f1 = src[1];
    uint4 d;
    d.x = packbf(f0.x, f0.y);
    d.y = packbf(f0.z, f0.w);
    d.z = packbf(f1.x, f1.y);
    d.w = packbf(f1.z, f1.w);
    ((uint4*)g_adjb)[i] = d;
}

// =============================================================================
// Prologue 2: u -> Q-aug cols 32..47, v -> K-aug cols 32..47 (permuted slots)
// =============================================================================
__global__ __launch_bounds__(256) void aug_kernel(const float* __restrict__ u,
                                                  const float* __restrict__ v) {
    int idx = blockIdx.x * 256 + threadIdx.x;
    if (idx >= HEADS * SEQ) return;
    int h = idx >> 11, n = idx & (SEQ - 1);
    unsigned uw[4], vw[4];
    #pragma unroll
    for (int i = 0; i < 4; i++) {
        uw[i] = packbf(u[((size_t)h * SEQ + n) * RNK + 2 * i],
                       u[((size_t)h * SEQ + n) * RNK + 2 * i + 1]);
        vw[i] = packbf(v[((size_t)h * RNK + 2 * i) * SEQ + n],
                       v[((size_t)h * RNK + 2 * i + 1) * SEQ + n]);
    }
    #pragma unroll
    for (int b = 0; b < BATCH; b++) {
        size_t base = ((size_t)(b * HEADS + h) * SEQ + n) * FEAT + 32;
        // logical pair (2i,2i+1) -> slot 4i ; zero pair (8+2i,..) -> slot 4i+2
        #pragma unroll
        for (int i = 0; i < 4; i++) {
            *(unsigned*)&g_qa[base + 4 * i]     = uw[i];
            *(unsigned*)&g_ka[base + 4 * i]     = vw[i];
            *(unsigned*)&g_qa[base + 4 * i + 2] = 0u;
            *(unsigned*)&g_ka[base + 4 * i + 2] = 0u;
        }
    }
}

// =============================================================================
// Kernel A: qkv = (x @ Wql + bql) @ Wqh + bqh -> bf16 permuted Q/K + V^T
// 16 rows per block, 256 threads; Wqh staged in smem (read once per block).
// =============================================================================
__global__ __launch_bounds__(256) void qkv_kernel(
    const float* __restrict__ x, const float* __restrict__ Wql,
    const float* __restrict__ bql, const float* __restrict__ Wqh,
    const float* __restrict__ bqh)
{
    __shared__ float xs[16 * HDIM];     // 8 KB
    __shared__ float wqh[24 * 384];     // 36 KB
    __shared__ float ts[16][25];

    const int tid = threadIdx.x;
    const int row0 = blockIdx.x * 16;

    #pragma unroll
    for (int i = 0; i < 2; i++)
        ((float4*)xs)[tid + i * 256] = ((const float4*)(x + (size_t)row0 * HDIM))[tid + i * 256];
    #pragma unroll
    for (int i = 0; i < 9; i++)
        ((float4*)wqh)[tid + i * 256] = ((const float4*)Wqh)[tid + i * 256];
    __syncthreads();

    // phase 1: warp w handles rows 2w, 2w+1; lanes 0..23 -> rank channel
    const int warp = tid >> 5, lane = tid & 31;
    if (lane < 24) {
        #pragma unroll
        for (int r2 = 0; r2 < 2; r2++) {
            int row = warp * 2 + r2;
            const float* xr = xs + row * HDIM;
            float a0 = 0.f, a1 = 0.f, a2 = 0.f, a3 = 0.f;
            #pragma unroll
            for (int d = 0; d < HDIM; d += 4) {
                a0 = fmaf(xr[d + 0], __ldg(&Wql[(d + 0) * 24 + lane]), a0);
                a1 = fmaf(xr[d + 1], __ldg(&Wql[(d + 1) * 24 + lane]), a1);
                a2 = fmaf(xr[d + 2], __ldg(&Wql[(d + 2) * 24 + lane]), a2);
                a3 = fmaf(xr[d + 3], __ldg(&Wql[(d + 3) * 24 + lane]), a3);
            }
            ts[row][lane] = (a0 + a1) + (a2 + a3) + bql[lane];
        }
    }
    __syncthreads();

    const int b  = row0 >> 11;
    const int n0 = row0 & (SEQ - 1);
    const float qscale = 0.17677669529663687f;   // 1/sqrt(32)

    for (int c = tid; c < 384; c += 256) {
        float wv[24];
        #pragma unroll
        for (int r = 0; r < 24; r++) wv[r] = wqh[r * 384 + c];
        const float bias = bqh[c];
        const int which = c >> 7;
        const int cc = c & 127;
        const int hh = cc >> 5, dd = cc & 31;

        float acc[16];
        #pragma unroll
        for (int row = 0; row < 16; row++) {
            float a = bias;
            #pragma unroll
            for (int r = 0; r < 24; r++) a = fmaf(ts[row][r], wv[r], a);
            acc[row] = a;
        }

        if (which < 2) {
            const int fslot = perm16(dd);
            __nv_bfloat16* dst = (which == 0) ? g_qa : g_ka;
            const float sc = (which == 0) ? qscale : 1.0f;
            size_t base = ((size_t)(b * HEADS + hh) * SEQ + n0) * FEAT + fslot;
            #pragma unroll
            for (int row = 0; row < 16; row++)
                dst[base + (size_t)row * FEAT] = __float2bfloat16(acc[row] * sc);
        } else {
            size_t base = ((size_t)(b * HEADS + hh) * HD + dd) * SEQ;
            #pragma unroll
            for (int row = 0; row < 16; row++)
                g_vt[base + perm16(n0 + row)] = __float2bfloat16(acc[row]);
        }
    }
}

// =============================================================================
// Kernel B: tensor-core attention. QTILE=32, CHUNK=64, 128 threads.
// warps (0,1): q rows [0,16),[16,32) on keys [0,32) of chunk
// warps (2,3): same q rows on keys [32,64); combined via smem at the end.
// =============================================================================
__global__ __launch_bounds__(128, 6) void attn_kernel(const float* __restrict__ adj_scale)
{
    __shared__ __nv_bfloat16 Ks[CHUNK * KPAD];     // 6 KB   [key][feat-slot]
    __shared__ __nv_bfloat16 Vts[HD * VPAD];       // 5 KB   [d][key-slot]
    __shared__ __nv_bfloat16 Adjs[QTILE * APAD];   // 4.5 KB [q][key] (unpermuted)
    __shared__ float OsumS[2][16][33];             // 4.1 KB
    __shared__ float rsS[2][16];

    const int tid  = threadIdx.x;
    const int lane = tid & 31;
    const int warp = tid >> 5;
    const int gid  = lane >> 2;
    const int tig  = lane & 3;
    const int h = blockIdx.y, b = blockIdx.z;
    const int q0 = blockIdx.x * QTILE;
    const int qrow  = (warp & 1) * 16;     // q-row offset in tile
    const int koff  = (warp >> 1) * 32;    // key offset in chunk

    const size_t bh     = (size_t)(b * HEADS + h);
    const size_t krow0  = bh * SEQ;
    const size_t vtrow0 = bh * HD;
    const float  cscale = log1pf(expf(adj_scale[0]));

    unsigned ksb = (unsigned)__cvta_generic_to_shared(Ks);
    unsigned vsb = (unsigned)__cvta_generic_to_shared(Vts);
    unsigned asb = (unsigned)__cvta_generic_to_shared(Adjs);

    // --- Q A-fragments (permuted global layout -> uint2 loads) ---
    unsigned qa[3][4];
    {
        const __nv_bfloat16* q0p = g_qa + (krow0 + q0 + qrow + gid) * FEAT;
        #pragma unroll
        for (int kk = 0; kk < 3; kk++) {
            uint2 t0 = *(const uint2*)(q0p + 16 * kk + 4 * tig);
            uint2 t1 = *(const uint2*)(q0p + 8 * FEAT + 16 * kk + 4 * tig);
            qa[kk][0] = t0.x; qa[kk][1] = t1.x; qa[kk][2] = t0.y; qa[kk][3] = t1.y;
        }
    }

    float o[4][4];
    #pragma unroll
    for (int i = 0; i < 4; i++)
        #pragma unroll
        for (int j = 0; j < 4; j++) o[i][j] = 0.f;
    float rs0 = 0.f, rs1 = 0.f;

    for (int j0 = 0; j0 < SEQ; j0 += CHUNK) {
        __syncthreads();
        // ---- async staging ----
        #pragma unroll
        for (int i = 0; i < 3; i++) {            // K: 64x48 el = 384 uint4
            int e = tid + i * 128, r = e / 6, c = e - r * 6;
            cp16(ksb + (r * KPAD + c * 8) * 2,
                 g_ka + (krow0 + j0 + r) * FEAT + c * 8);
        }
        #pragma unroll
        for (int i = 0; i < 2; i++) {            // V^T: 32x64 el = 256 uint4
            int e = tid + i * 128, r = e >> 3, c = e & 7;
            cp16(vsb + (r * VPAD + c * 8) * 2,
                 g_vt + (vtrow0 + r) * SEQ + j0 + c * 8);
        }
        #pragma unroll
        for (int i = 0; i < 2; i++) {            // adj: 32x64 el = 256 uint4
            int e = tid + i * 128, r = e >> 3, c = e & 7;
            cp16(asb + (r * APAD + c * 8) * 2,
                 g_adjb + (size_t)(q0 + r) * SEQ + j0 + c * 8);
        }
        asm volatile("cp.async.commit_group;");
        asm volatile("cp.async.wait_group 0;");
        __syncthreads();

        #pragma unroll
        for (int gl = 0; gl < 2; gl++) {         // 16 keys per gl
            float p[2][4];
            #pragma unroll
            for (int t = 0; t < 2; t++) {
                const int kr = koff + gl * 16 + t * 8;   // key row base
                float c0 = 0.f, c1 = 0.f, c2 = 0.f, c3 = 0.f;
                #pragma unroll
                for (int kk = 0; kk < 3; kk++) {
                    uint2 bb = *(const uint2*)&Ks[(kr + gid) * KPAD + 16 * kk + 4 * tig];
                    mma16816(c0, c1, c2, c3,
                             qa[kk][0], qa[kk][1], qa[kk][2], qa[kk][3], bb.x, bb.y);
                }
                unsigned au0 = *(const unsigned*)&Adjs[(qrow + gid) * APAD + kr + 2 * tig];
                unsigned au1 = *(const unsigned*)&Adjs[(qrow + gid + 8) * APAD + kr + 2 * tig];
                c0 = __expf(fmaf(cscale, bflo(au0), c0));
                c1 = __expf(fmaf(cscale, bfhi(au0), c1));
                c2 = __expf(fmaf(cscale, bflo(au1), c2));
                c3 = __expf(fmaf(cscale, bfhi(au1), c3));
                rs0 += c0 + c1;
                rs1 += c2 + c3;
                p[t][0] = c0; p[t][1] = c1; p[t][2] = c2; p[t][3] = c3;
            }
            unsigned pa0 = packbf(p[0][0], p[0][1]);
            unsigned pa1 = packbf(p[0][2], p[0][3]);
            unsigned pa2 = packbf(p[1][0], p[1][1]);
            unsigned pa3 = packbf(p[1][2], p[1][3]);
            #pragma unroll
            for (int nf = 0; nf < 4; nf++) {
                uint2 bb = *(const uint2*)&Vts[(8 * nf + gid) * VPAD + koff + 16 * gl + 4 * tig];
                mma16816(o[nf][0], o[nf][1], o[nf][2], o[nf][3],
                         pa0, pa1, pa2, pa3, bb.x, bb.y);
            }
        }
    }

    // quad-reduce row sums (cols spread over tig)
    rs0 += __shfl_xor_sync(0xffffffffu, rs0, 1);
    rs0 += __shfl_xor_sync(0xffffffffu, rs0, 2);
    rs1 += __shfl_xor_sync(0xffffffffu, rs1, 1);
    rs1 += __shfl_xor_sync(0xffffffffu, rs1, 2);

    // cross-warp (key-half) combine
    __syncthreads();
    if (warp >= 2) {
        const int w = warp & 1;
        #pragma unroll
        for (int nf = 0; nf < 4; nf++) {
            OsumS[w][gid][8 * nf + 2 * tig]     = o[nf][0];
            OsumS[w][gid][8 * nf + 2 * tig + 1] = o[nf][1];
            OsumS[w][gid + 8][8 * nf + 2 * tig]     = o[nf][2];
            OsumS[w][gid + 8][8 * nf + 2 * tig + 1] = o[nf][3];
        }
        if (tig == 0) { rsS[w][gid] = rs0; rsS[w][gid + 8] = rs1; }
    }
    __syncthreads();
    if (warp < 2) {
        const int w = warp;
        #pragma unroll
        for (int nf = 0; nf < 4; nf++) {
            o[nf][0] += OsumS[w][gid][8 * nf + 2 * tig];
            o[nf][1] += OsumS[w][gid][8 * nf + 2 * tig + 1];
            o[nf][2] += OsumS[w][gid + 8][8 * nf + 2 * tig];
            o[nf][3] += OsumS[w][gid + 8][8 * nf + 2 * tig + 1];
        }
        rs0 += rsS[w][gid];
        rs1 += rsS[w][gid + 8];
        const float i0 = 1.f / rs0, i1 = 1.f / rs1;
        const size_t orow = bh * SEQ + q0 + qrow + gid;
        #pragma unroll
        for (int nf = 0; nf < 4; nf++) {
            *(float2*)&g_o[orow * HD + 8 * nf + 2 * tig] =
                make_float2(o[nf][0] * i0, o[nf][1] * i0);
            *(float2*)&g_o[(orow + 8) * HD + 8 * nf + 2 * tig] =
                make_float2(o[nf][2] * i1, o[nf][3] * i1);
        }
    }
}

// =============================================================================
// Kernel C: output projection + residual + LayerNorm + analytic reg_loss
// =============================================================================
__device__ __forceinline__ float block_sum_128(float val, float* red4) {
    #pragma unroll
    for (int off = 16; off > 0; off >>= 1)
        val += __shfl_xor_sync(0xffffffffu, val, off);
    const int w = threadIdx.x >> 5;
    if ((threadIdx.x & 31) == 0) red4[w] = val;
    __syncthreads();
    val = red4[0] + red4[1] + red4[2] + red4[3];
    __syncthreads();
    return val;
}

__global__ __launch_bounds__(128) void epi_kernel(
    const float* __restrict__ x, const float* __restrict__ Wol,
    const float* __restrict__ bol, const float* __restrict__ Woh,
    const float* __restrict__ boh, const float* __restrict__ gamma,
    const float* __restrict__ beta, const float* __restrict__ log_reg_w,
    float* __restrict__ out, int out_size)
{
    __shared__ float sm[4][8];
    __shared__ float t8[8];
    __shared__ float red4[4];

    const int row = blockIdx.x;
    const int d   = threadIdx.x;
    const int b   = row >> 11;
    const int n   = row & (SEQ - 1);
    const int h   = d >> 5, dd = d & 31;
    const int w   = d >> 5, lane = d & 31;

    const float o_d = g_o[(((size_t)(b * HEADS + h)) * SEQ + n) * HD + dd];

    float w8[8];
    {
        const float4* wp = (const float4*)(Wol + d * RNK);
        float4 t0 = wp[0], t1 = wp[1];
        w8[0] = t0.x; w8[1] = t0.y; w8[2] = t0.z; w8[3] = t0.w;
        w8[4] = t1.x; w8[5] = t1.y; w8[6] = t1.z; w8[7] = t1.w;
    }
    #pragma unroll
    for (int r = 0; r < 8; r++) {
        float p = o_d * w8[r];
        #pragma unroll
        for (int off = 16; off > 0; off >>= 1)
            p += __shfl_xor_sync(0xffffffffu, p, off);
        if (lane == 0) sm[w][r] = p;
    }
    __syncthreads();
    if (d < 8) t8[d] = sm[0][d] + sm[1][d] + sm[2][d] + sm[3][d] + bol[d];
    __syncthreads();

    float o2 = boh[d];
    #pragma unroll
    for (int r = 0; r < 8; r++) o2 = fmaf(t8[r], Woh[r * HDIM + d], o2);
    float y = o2 + x[(size_t)row * HDIM + d];

    float mu = block_sum_128(y, red4) * (1.0f / HDIM);
    float dy = y - mu;
    float var = block_sum_128(dy * dy, red4) * (1.0f / HDIM);
    float res = dy * rsqrtf(var + 1e-5f) * gamma[d] + beta[d];
    out[(size_t)row * HDIM + d] = res;

    if (row == 0 && d == 0) {
        float reg = expf(log_reg_w[0]) * (1.0f / (float)SEQ);
        for (int i = NTOT; i < out_size; i++) out[i] = reg;
    }
}

// =============================================================================
extern "C" void kernel_launch(void* const* d_in, const int* in_sizes, int n_in,
                              void* d_out, int out_size)
{
    const float* x         = (const float*)d_in[0];
    const float* Wql       = (const float*)d_in[1];
    const float* bql       = (const float*)d_in[2];
    const float* Wqh       = (const float*)d_in[3];
    const float* bqh       = (const float*)d_in[4];
    const float* u         = (const float*)d_in[5];
    const float* v         = (const float*)d_in[6];
    const float* adj_scale = (const float*)d_in[7];
    const float* Wol       = (const float*)d_in[8];
    const float* bol       = (const float*)d_in[9];
    const float* Woh       = (const float*)d_in[10];
    const float* boh       = (const float*)d_in[11];
    const float* gamma     = (const float*)d_in[12];
    const float* beta      = (const float*)d_in[13];
    const float* log_reg_w = (const float*)d_in[14];
    const float* adj_prior = (const float*)d_in[15];
    float* out = (float*)d_out;

    adjcvt_kernel<<<(SEQ * SEQ) / (8 * 256), 256>>>(adj_prior);
    aug_kernel<<<(HEADS * SEQ + 255) / 256, 256>>>(u, v);
    qkv_kernel<<<(BATCH * SEQ) / 16, 256>>>(x, Wql, bql, Wqh, bqh);
    attn_kernel<<<dim3(SEQ / QTILE, HEADS, BATCH), 128>>>(adj_scale);
    epi_kernel<<<BATCH * SEQ, 128>>>(x, Wol, bol, Woh, boh, gamma, beta,
                                     log_reg_w, out, out_size);
}

// round 4
// speedup vs baseline: 1.2462x; 1.2462x over previous
#include <cuda_runtime.h>
#include <cuda_bf16.h>
#include <math.h>

#define BATCH 4
#define SEQ   2048
#define HDIM  128
#define HEADS 4
#define HD    32
#define RNK   8
#define FEAT  48            // 32 (qk) + 8 (u/v bias) + 8 zero pad
#define KPAD  48            // Ks row stride (elements) — conflict-free LDS.64
#define VPAD  80            // Vt row stride
#define APAD  72            // adj row stride
#define QTILE 64
#define CHUNK 64
#define NCH   (SEQ / CHUNK)
#define NTOT  (BATCH * SEQ * HDIM)

// smem stage layout (bytes)
#define K_OFF    0
#define K_BYTES  (CHUNK * KPAD * 2)            // 6144
#define V_OFF    K_BYTES                       // 6144
#define V_BYTES  (HD * VPAD * 2)               // 5120
#define A_OFF    (V_OFF + V_BYTES)             // 11264
#define A_BYTES  (QTILE * APAD * 2)            // 9216
#define STAGE_SZ (A_OFF + A_BYTES)             // 20480

// Permuted element layout inside every 16-element group (feature dim of Q/K,
// key dim of V^T): logical (2t+e) -> slot (4t+e); logical (8+2t+e) -> slot (4t+2+e).
// Each m16n8k16 B-operand (b0,b1) becomes one contiguous 8-byte LDS.

// ---------------- static device scratch ------------------------------------
__device__ __align__(16) __nv_bfloat16 g_qa[BATCH * HEADS * SEQ * FEAT];
__device__ __align__(16) __nv_bfloat16 g_ka[BATCH * HEADS * SEQ * FEAT];
__device__ __align__(16) __nv_bfloat16 g_vt[BATCH * HEADS * HD * SEQ];
__device__ __align__(16) __nv_bfloat16 g_adjb[SEQ * SEQ];
__device__ __align__(16) float         g_o[BATCH * HEADS * SEQ * HD];

// ---------------- helpers ---------------------------------------------------
__device__ __forceinline__ unsigned packbf(float lo, float hi) {
    unsigned r;
    asm("cvt.rn.bf16x2.f32 %0, %1, %2;" : "=r"(r) : "f"(hi), "f"(lo));
    return r;
}
__device__ __forceinline__ float bflo(unsigned u) { return __int_as_float(u << 16); }
__device__ __forceinline__ float bfhi(unsigned u) { return __int_as_float(u & 0xffff0000u); }

__device__ __host__ __forceinline__ int perm16(int c) {
    int g = c & ~15, c16 = c & 15;
    return g + 4 * ((c16 >> 1) & 3) + 2 * (c16 >> 3) + (c16 & 1);
}

__device__ __forceinline__ void mma16816(float& c0, float& c1, float& c2, float& c3,
                                         unsigned a0, unsigned a1, unsigned a2, unsigned a3,
                                         unsigned b0, unsigned b1) {
    asm volatile("mma.sync.aligned.m16n8k16.row.col.f32.bf16.bf16.f32 "
                 "{%0,%1,%2,%3}, {%4,%5,%6,%7}, {%8,%9}, {%0,%1,%2,%3};"
                 : "+f"(c0), "+f"(c1), "+f"(c2), "+f"(c3)
                 : "r"(a0), "r"(a1), "r"(a2), "r"(a3), "r"(b0), "r"(b1));
}

__device__ __forceinline__ void cp16(unsigned smem_dst, const void* gsrc) {
    asm volatile("cp.async.cg.shared.global [%0], [%1], 16;" :: "r"(smem_dst), "l"(gsrc));
}

// =============================================================================
// Prologue 1: adj fp32 -> bf16
// =============================================================================
__global__ __launch_bounds__(256) void adjcvt_kernel(const float* __restrict__ adj) {
    int i = blockIdx.x * 256 + threadIdx.x;
    const float4* src = (const float4*)adj + (size_t)i * 2;
    float4 f0 = src[0], f1 = src[1];
    uint4 d;
    d.x = packbf(f0.x, f0.y);
    d.y = packbf(f0.z, f0.w);
    d.z = packbf(f1.x, f1.y);
    d.w = packbf(f1.z, f1.w);
    ((uint4*)g_adjb)[i] = d;
}

// =============================================================================
// Prologue 2: u -> Q-aug cols 32..47, v -> K-aug cols 32..47 (permuted slots)
// =============================================================================
__global__ __launch_bounds__(256) void aug_kernel(const float* __restrict__ u,
                                                  const float* __restrict__ v) {
    int idx = blockIdx.x * 256 + threadIdx.x;
    if (idx >= HEADS * SEQ) return;
    int h = idx >> 11, n = idx & (SEQ - 1);
    unsigned uw[4], vw[4];
    #pragma unroll
    for (int i = 0; i < 4; i++) {
        uw[i] = packbf(u[((size_t)h * SEQ + n) * RNK + 2 * i],
                       u[((size_t)h * SEQ + n) * RNK + 2 * i + 1]);
        vw[i] = packbf(v[((size_t)h * RNK + 2 * i) * SEQ + n],
                       v[((size_t)h * RNK + 2 * i + 1) * SEQ + n]);
    }
    #pragma unroll
    for (int b = 0; b < BATCH; b++) {
        size_t base = ((size_t)(b * HEADS + h) * SEQ + n) * FEAT + 32;
        #pragma unroll
        for (int i = 0; i < 4; i++) {
            *(unsigned*)&g_qa[base + 4 * i]     = uw[i];
            *(unsigned*)&g_ka[base + 4 * i]     = vw[i];
            *(unsigned*)&g_qa[base + 4 * i + 2] = 0u;
            *(unsigned*)&g_ka[base + 4 * i + 2] = 0u;
        }
    }
}

// =============================================================================
// Kernel A: qkv = (x @ Wql + bql) @ Wqh + bqh -> bf16 permuted Q/K + V^T
// (round-1/2 measured-fast shape: 4 rows per block, 128 threads)
// =============================================================================
__global__ __launch_bounds__(128) void qkv_kernel(
    const float* __restrict__ x, const float* __restrict__ Wql,
    const float* __restrict__ bql, const float* __restrict__ Wqh,
    const float* __restrict__ bqh)
{
    __shared__ float xs[4 * HDIM];
    __shared__ float ws[HDIM * 24];
    __shared__ float ts[4][24];

    const int tid  = threadIdx.x;
    const int row0 = blockIdx.x * 4;

    ((float4*)xs)[tid] = ((const float4*)(x + (size_t)row0 * HDIM))[tid];
    #pragma unroll
    for (int i = 0; i < 6; i++)
        ((float4*)ws)[tid + i * 128] = ((const float4*)Wql)[tid + i * 128];
    __syncthreads();

    const int w = tid >> 5, lane = tid & 31;
    if (lane < 24) {
        float a0 = 0.f, a1 = 0.f, a2 = 0.f, a3 = 0.f;
        const float* xr = xs + w * HDIM;
        #pragma unroll
        for (int d = 0; d < HDIM; d += 4) {
            a0 = fmaf(xr[d + 0], ws[(d + 0) * 24 + lane], a0);
            a1 = fmaf(xr[d + 1], ws[(d + 1) * 24 + lane], a1);
            a2 = fmaf(xr[d + 2], ws[(d + 2) * 24 + lane], a2);
            a3 = fmaf(xr[d + 3], ws[(d + 3) * 24 + lane], a3);
        }
        ts[w][lane] = (a0 + a1) + (a2 + a3) + bql[lane];
    }
    __syncthreads();

    const int b  = row0 >> 11;
    const int n0 = row0 & (SEQ - 1);
    const float qscale = 0.17677669529663687f;   // 1/sqrt(32)

    for (int c = tid; c < 384; c += 128) {
        float acc0 = bqh[c], acc1 = acc0, acc2 = acc0, acc3 = acc0;
        #pragma unroll
        for (int r = 0; r < 24; r++) {
            float wv = Wqh[r * 384 + c];
            acc0 = fmaf(ts[0][r], wv, acc0);
            acc1 = fmaf(ts[1][r], wv, acc1);
            acc2 = fmaf(ts[2][r], wv, acc2);
            acc3 = fmaf(ts[3][r], wv, acc3);
        }
        const int which = c >> 7;
        const int cc = c & 127;
        const int hh = cc >> 5, dd = cc & 31;
        if (which < 2) {
            const int fslot = perm16(dd);
            __nv_bfloat16* dst = (which == 0) ? g_qa : g_ka;
            const float sc = (which == 0) ? qscale : 1.0f;
            size_t base = ((size_t)(b * HEADS + hh) * SEQ + n0) * FEAT + fslot;
            dst[base +      0] = __float2bfloat16(acc0 * sc);
            dst[base +   FEAT] = __float2bfloat16(acc1 * sc);
            dst[base + 2*FEAT] = __float2bfloat16(acc2 * sc);
            dst[base + 3*FEAT] = __float2bfloat16(acc3 * sc);
        } else {
            // V^T [b,h,d,n] with permuted n-slots; n0 is a multiple of 4, and
            // logical pairs stay adjacent under perm16.
            unsigned lo = packbf(acc0, acc1), hi = packbf(acc2, acc3);
            size_t base = ((size_t)(b * HEADS + hh) * HD + dd) * SEQ;
            *(unsigned*)&g_vt[base + perm16(n0)]     = lo;
            *(unsigned*)&g_vt[base + perm16(n0 + 2)] = hi;
        }
    }
}

// =============================================================================
// Kernel B: tensor-core attention. QTILE=64, CHUNK=64, 256 threads.
// 8 warps = 4 q-subtiles x 2 key-halves; double-buffered cp.async staging.
// =============================================================================
__global__ __launch_bounds__(256, 3) void attn_kernel(const float* __restrict__ adj_scale)
{
    __shared__ __align__(16) char smem_raw[2 * STAGE_SZ];   // 40 KB

    const int tid  = threadIdx.x;
    const int lane = tid & 31;
    const int warp = tid >> 5;
    const int gid  = lane >> 2;
    const int tig  = lane & 3;
    const int h = blockIdx.y, b = blockIdx.z;
    const int q0 = blockIdx.x * QTILE;
    const int qrow = (warp & 3) * 16;      // q-row offset in tile
    const int koff = (warp >> 2) * 32;     // key offset in chunk

    const size_t bh     = (size_t)(b * HEADS + h);
    const size_t krow0  = bh * SEQ;
    const size_t vtrow0 = bh * HD;
    const float  cscale = log1pf(expf(adj_scale[0]));

    const unsigned sbase = (unsigned)__cvta_generic_to_shared(smem_raw);

    // --- Q A-fragments (permuted global layout -> uint2 loads) ---
    unsigned qa[3][4];
    {
        const __nv_bfloat16* q0p = g_qa + (krow0 + q0 + qrow + gid) * FEAT;
        #pragma unroll
        for (int kk = 0; kk < 3; kk++) {
            uint2 t0 = *(const uint2*)(q0p + 16 * kk + 4 * tig);
            uint2 t1 = *(const uint2*)(q0p + 8 * FEAT + 16 * kk + 4 * tig);
            qa[kk][0] = t0.x; qa[kk][1] = t1.x; qa[kk][2] = t0.y; qa[kk][3] = t1.y;
        }
    }

    float o[4][4];
    #pragma unroll
    for (int i = 0; i < 4; i++)
        #pragma unroll
        for (int j = 0; j < 4; j++) o[i][j] = 0.f;
    float rs0 = 0.f, rs1 = 0.f;

    // staging helper
    auto stage = [&](int jc, int s) {
        const int j0 = jc * CHUNK;
        const unsigned kd = sbase + s * STAGE_SZ + K_OFF;
        const unsigned vd = sbase + s * STAGE_SZ + V_OFF;
        const unsigned ad = sbase + s * STAGE_SZ + A_OFF;
        {   // K: 64 x 48 el = 384 uint4
            int e = tid, r = e / 6, c = e - r * 6;
            cp16(kd + (r * KPAD + c * 8) * 2, g_ka + (krow0 + j0 + r) * FEAT + c * 8);
            e = tid + 256;
            if (e < 384) {
                r = e / 6; c = e - r * 6;
                cp16(kd + (r * KPAD + c * 8) * 2, g_ka + (krow0 + j0 + r) * FEAT + c * 8);
            }
        }
        {   // V^T: 32 x 64 el = 256 uint4
            int r = tid >> 3, c = tid & 7;
            cp16(vd + (r * VPAD + c * 8) * 2, g_vt + (vtrow0 + r) * SEQ + j0 + c * 8);
        }
        #pragma unroll
        for (int i = 0; i < 2; i++) {   // adj: 64 x 64 el = 512 uint4
            int e = tid + i * 256, r = e >> 3, c = e & 7;
            cp16(ad + (r * APAD + c * 8) * 2, g_adjb + (size_t)(q0 + r) * SEQ + j0 + c * 8);
        }
    };

    stage(0, 0);
    asm volatile("cp.async.commit_group;");

    for (int jc = 0; jc < NCH; jc++) {
        const int s = jc & 1;
        if (jc + 1 < NCH) {
            stage(jc + 1, s ^ 1);
            asm volatile("cp.async.commit_group;");
            asm volatile("cp.async.wait_group 1;");
        } else {
            asm volatile("cp.async.wait_group 0;");
        }
        __syncthreads();

        const __nv_bfloat16* Ks   = (const __nv_bfloat16*)(smem_raw + s * STAGE_SZ + K_OFF);
        const __nv_bfloat16* Vts  = (const __nv_bfloat16*)(smem_raw + s * STAGE_SZ + V_OFF);
        const __nv_bfloat16* Adjs = (const __nv_bfloat16*)(smem_raw + s * STAGE_SZ + A_OFF);

        #pragma unroll
        for (int gl = 0; gl < 2; gl++) {         // 16 keys per gl
            float p[2][4];
            #pragma unroll
            for (int t = 0; t < 2; t++) {
                const int kr = koff + gl * 16 + t * 8;
                float c0 = 0.f, c1 = 0.f, c2 = 0.f, c3 = 0.f;
                #pragma unroll
                for (int kk = 0; kk < 3; kk++) {
                    uint2 bb = *(const uint2*)&Ks[(kr + gid) * KPAD + 16 * kk + 4 * tig];
                    mma16816(c0, c1, c2, c3,
                             qa[kk][0], qa[kk][1], qa[kk][2], qa[kk][3], bb.x, bb.y);
                }
                unsigned au0 = *(const unsigned*)&Adjs[(qrow + gid) * APAD + kr + 2 * tig];
                unsigned au1 = *(const unsigned*)&Adjs[(qrow + gid + 8) * APAD + kr + 2 * tig];
                c0 = __expf(fmaf(cscale, bflo(au0), c0));
                c1 = __expf(fmaf(cscale, bfhi(au0), c1));
                c2 = __expf(fmaf(cscale, bflo(au1), c2));
                c3 = __expf(fmaf(cscale, bfhi(au1), c3));
                rs0 += c0 + c1;
                rs1 += c2 + c3;
                p[t][0] = c0; p[t][1] = c1; p[t][2] = c2; p[t][3] = c3;
            }
            unsigned pa0 = packbf(p[0][0], p[0][1]);
            unsigned pa1 = packbf(p[0][2], p[0][3]);
            unsigned pa2 = packbf(p[1][0], p[1][1]);
            unsigned pa3 = packbf(p[1][2], p[1][3]);
            #pragma unroll
            for (int nf = 0; nf < 4; nf++) {
                uint2 bb = *(const uint2*)&Vts[(8 * nf + gid) * VPAD + koff + 16 * gl + 4 * tig];
                mma16816(o[nf][0], o[nf][1], o[nf][2], o[nf][3],
                         pa0, pa1, pa2, pa3, bb.x, bb.y);
            }
        }
        __syncthreads();
    }

    // quad-reduce row sums (cols spread over tig)
    rs0 += __shfl_xor_sync(0xffffffffu, rs0, 1);
    rs0 += __shfl_xor_sync(0xffffffffu, rs0, 2);
    rs1 += __shfl_xor_sync(0xffffffffu, rs1, 1);
    rs1 += __shfl_xor_sync(0xffffffffu, rs1, 2);

    // cross-warp (key-half) combine — alias scratch onto stage-0 buffers
    float* OsumS = (float*)smem_raw;               // [64][33] floats = 8448 B
    float* rsS   = (float*)(smem_raw + 8448);      // [64] floats
    const int orow_l = qrow + gid;                 // 0..63 (this thread's first row)

    if (warp >= 4) {
        #pragma unroll
        for (int nf = 0; nf < 4; nf++) {
            OsumS[orow_l * 33 + 8 * nf + 2 * tig]           = o[nf][0];
            OsumS[orow_l * 33 + 8 * nf + 2 * tig + 1]       = o[nf][1];
            OsumS[(orow_l + 8) * 33 + 8 * nf + 2 * tig]     = o[nf][2];
            OsumS[(orow_l + 8) * 33 + 8 * nf + 2 * tig + 1] = o[nf][3];
        }
        if (tig == 0) { rsS[orow_l] = rs0; rsS[orow_l + 8] = rs1; }
    }
    __syncthreads();
    if (warp < 4) {
        #pragma unroll
        for (int nf = 0; nf < 4; nf++) {
            o[nf][0] += OsumS[orow_l * 33 + 8 * nf + 2 * tig];
            o[nf][1] += OsumS[orow_l * 33 + 8 * nf + 2 * tig + 1];
            o[nf][2] += OsumS[(orow_l + 8) * 33 + 8 * nf + 2 * tig];
            o[nf][3] += OsumS[(orow_l + 8) * 33 + 8 * nf + 2 * tig + 1];
        }
        rs0 += rsS[orow_l];
        rs1 += rsS[orow_l + 8];
        const float i0 = 1.f / rs0, i1 = 1.f / rs1;
        const size_t orow = bh * SEQ + q0 + orow_l;
        #pragma unroll
        for (int nf = 0; nf < 4; nf++) {
            *(float2*)&g_o[orow * HD + 8 * nf + 2 * tig] =
                make_float2(o[nf][0] * i0, o[nf][1] * i0);
            *(float2*)&g_o[(orow + 8) * HD + 8 * nf + 2 * tig] =
                make_float2(o[nf][2] * i1, o[nf][3] * i1);
        }
    }
}

// =============================================================================
// Kernel C: output projection + residual + LayerNorm + analytic reg_loss
// =============================================================================
__device__ __forceinline__ float block_sum_128(float val, float* red4) {
    #pragma unroll
    for (int off = 16; off > 0; off >>= 1)
        val += __shfl_xor_sync(0xffffffffu, val, off);
    const int w = threadIdx.x >> 5;
    if ((threadIdx.x & 31) == 0) red4[w] = val;
    __syncthreads();
    val = red4[0] + red4[1] + red4[2] + red4[3];
    __syncthreads();
    return val;
}

__global__ __launch_bounds__(128) void epi_kernel(
    const float* __restrict__ x, const float* __restrict__ Wol,
    const float* __restrict__ bol, const float* __restrict__ Woh,
    const float* __restrict__ boh, const float* __restrict__ gamma,
    const float* __restrict__ beta, const float* __restrict__ log_reg_w,
    float* __restrict__ out, int out_size)
{
    __shared__ float sm[4][8];
    __shared__ float t8[8];
    __shared__ float red4[4];

    const int row = blockIdx.x;
    const int d   = threadIdx.x;
    const int b   = row >> 11;
    const int n   = row & (SEQ - 1);
    const int h   = d >> 5, dd = d & 31;
    const int w   = d >> 5, lane = d & 31;

    const float o_d = g_o[(((size_t)(b * HEADS + h)) * SEQ + n) * HD + dd];

    float w8[8];
    {
        const float4* wp = (const float4*)(Wol + d * RNK);
        float4 t0 = wp[0], t1 = wp[1];
        w8[0] = t0.x; w8[1] = t0.y; w8[2] = t0.z; w8[3] = t0.w;
        w8[4] = t1.x; w8[5] = t1.y; w8[6] = t1.z; w8[7] = t1.w;
    }
    #pragma unroll
    for (int r = 0; r < 8; r++) {
        float p = o_d * w8[r];
        #pragma unroll
        for (int off = 16; off > 0; off >>= 1)
            p += __shfl_xor_sync(0xffffffffu, p, off);
        if (lane == 0) sm[w][r] = p;
    }
    __syncthreads();
    if (d < 8) t8[d] = sm[0][d] + sm[1][d] + sm[2][d] + sm[3][d] + bol[d];
    __syncthreads();

    float o2 = boh[d];
    #pragma unroll
    for (int r = 0; r < 8; r++) o2 = fmaf(t8[r], Woh[r * HDIM + d], o2);
    float y = o2 + x[(size_t)row * HDIM + d];

    float mu = block_sum_128(y, red4) * (1.0f / HDIM);
    float dy = y - mu;
    float var = block_sum_128(dy * dy, red4) * (1.0f / HDIM);
    float res = dy * rsqrtf(var + 1e-5f) * gamma[d] + beta[d];
    out[(size_t)row * HDIM + d] = res;

    if (row == 0 && d == 0) {
        float reg = expf(log_reg_w[0]) * (1.0f / (float)SEQ);
        for (int i = NTOT; i < out_size; i++) out[i] = reg;
    }
}

// =============================================================================
extern "C" void kernel_launch(void* const* d_in, const int* in_sizes, int n_in,
                              void* d_out, int out_size)
{
    const float* x         = (const float*)d_in[0];
    const float* Wql       = (const float*)d_in[1];
    const float* bql       = (const float*)d_in[2];
    const float* Wqh       = (const float*)d_in[3];
    const float* bqh       = (const float*)d_in[4];
    const float* u         = (const float*)d_in[5];
    const float* v         = (const float*)d_in[6];
    const float* adj_scale = (const float*)d_in[7];
    const float* Wol       = (const float*)d_in[8];
    const float* bol       = (const float*)d_in[9];
    const float* Woh       = (const float*)d_in[10];
    const float* boh       = (const float*)d_in[11];
    const float* gamma     = (const float*)d_in[12];
    const float* beta      = (const float*)d_in[13];
    const float* log_reg_w = (const float*)d_in[14];
    const float* adj_prior = (const float*)d_in[15];
    float* out = (float*)d_out;

    adjcvt_kernel<<<(SEQ * SEQ) / (8 * 256), 256>>>(adj_prior);
    aug_kernel<<<(HEADS * SEQ + 255) / 256, 256>>>(u, v);
    qkv_kernel<<<(BATCH * SEQ) / 4, 128>>>(x, Wql, bql, Wqh, bqh);
    attn_kernel<<<dim3(SEQ / QTILE, HEADS, BATCH), 256>>>(adj_scale);
    epi_kernel<<<BATCH * SEQ, 128>>>(x, Wol, bol, Woh, boh, gamma, beta,
                                     log_reg_w, out, out_size);
}

// round 5
// speedup vs baseline: 1.3733x; 1.1020x over previous
#include <cuda_runtime.h>
#include <cuda_bf16.h>
#include <math.h>

#define BATCH 4
#define SEQ   2048
#define HDIM  128
#define HEADS 4
#define HD    32
#define RNK   8
#define FEAT  48            // 32 (qk) + 8 (u/v bias) + 8 zero pad
#define KPAD  48
#define VPAD  80
#define APAD  72
#define QTILE 64
#define CHUNK 64
#define NCH   (SEQ / CHUNK)
#define NTOT  (BATCH * SEQ * HDIM)
#define LOG2E 1.4426950408889634f

// smem stage layout (bytes)
#define K_OFF    0
#define K_BYTES  (CHUNK * KPAD * 2)            // 6144
#define V_OFF    K_BYTES
#define V_BYTES  (HD * VPAD * 2)               // 5120
#define A_OFF    (V_OFF + V_BYTES)
#define A_BYTES  (QTILE * APAD * 2)            // 9216
#define STAGE_SZ (A_OFF + A_BYTES)             // 20480

// ---------------- static device scratch ------------------------------------
__device__ __align__(16) __nv_bfloat16 g_qa[BATCH * HEADS * SEQ * FEAT];
__device__ __align__(16) __nv_bfloat16 g_ka[BATCH * HEADS * SEQ * FEAT];
__device__ __align__(16) __nv_bfloat16 g_vt[BATCH * HEADS * HD * SEQ];
__device__ __align__(16) __nv_bfloat16 g_adjb[SEQ * SEQ];    // pre-scaled by softplus*log2e
__device__ __align__(16) float         g_o[BATCH * HEADS * SEQ * HD];
__device__ __align__(16) float         g_t[BATCH * SEQ * 24];   // low-rank activations

// ---------------- helpers ---------------------------------------------------
__device__ __forceinline__ unsigned packbf(float lo, float hi) {
    unsigned r;
    asm("cvt.rn.bf16x2.f32 %0, %1, %2;" : "=r"(r) : "f"(hi), "f"(lo));
    return r;
}
__device__ __forceinline__ float bflo(unsigned u) { return __int_as_float(u << 16); }
__device__ __forceinline__ float bfhi(unsigned u) { return __int_as_float(u & 0xffff0000u); }
__device__ __forceinline__ float ex2f(float x) {
    float y;
    asm("ex2.approx.f32 %0, %1;" : "=f"(y) : "f"(x));
    return y;
}

__device__ __host__ __forceinline__ int perm16(int c) {
    int g = c & ~15, c16 = c & 15;
    return g + 4 * ((c16 >> 1) & 3) + 2 * (c16 >> 3) + (c16 & 1);
}

__device__ __forceinline__ void mma16816(float& c0, float& c1, float& c2, float& c3,
                                         unsigned a0, unsigned a1, unsigned a2, unsigned a3,
                                         unsigned b0, unsigned b1) {
    asm volatile("mma.sync.aligned.m16n8k16.row.col.f32.bf16.bf16.f32 "
                 "{%0,%1,%2,%3}, {%4,%5,%6,%7}, {%8,%9}, {%0,%1,%2,%3};"
                 : "+f"(c0), "+f"(c1), "+f"(c2), "+f"(c3)
                 : "r"(a0), "r"(a1), "r"(a2), "r"(a3), "r"(b0), "r"(b1));
}

__device__ __forceinline__ void cp16(unsigned smem_dst, const void* gsrc) {
    asm volatile("cp.async.cg.shared.global [%0], [%1], 16;" :: "r"(smem_dst), "l"(gsrc));
}

// =============================================================================
// Prologue 1: adj fp32 -> bf16, pre-multiplied by softplus(adj_scale)*log2e
// =============================================================================
__global__ __launch_bounds__(256) void adjcvt_kernel(const float* __restrict__ adj,
                                                     const float* __restrict__ adj_scale) {
    const float cs = log1pf(expf(adj_scale[0])) * LOG2E;
    int i = blockIdx.x * 256 + threadIdx.x;
    const float4* src = (const float4*)adj + (size_t)i * 2;
    float4 f0 = src[0], f1 = src[1];
    uint4 d;
    d.x = packbf(f0.x * cs, f0.y * cs);
    d.y = packbf(f0.z * cs, f0.w * cs);
    d.z = packbf(f1.x * cs, f1.y * cs);
    d.w = packbf(f1.z * cs, f1.w * cs);
    ((uint4*)g_adjb)[i] = d;
}

// =============================================================================
// Prologue 2: u*log2e -> Q-aug cols 32..47, v -> K-aug cols 32..47 (permuted)
// =============================================================================
__global__ __launch_bounds__(256) void aug_kernel(const float* __restrict__ u,
                                                  const float* __restrict__ v) {
    int idx = blockIdx.x * 256 + threadIdx.x;
    if (idx >= HEADS * SEQ) return;
    int h = idx >> 11, n = idx & (SEQ - 1);
    unsigned uw[4], vw[4];
    #pragma unroll
    for (int i = 0; i < 4; i++) {
        uw[i] = packbf(u[((size_t)h * SEQ + n) * RNK + 2 * i] * LOG2E,
                       u[((size_t)h * SEQ + n) * RNK + 2 * i + 1] * LOG2E);
        vw[i] = packbf(v[((size_t)h * RNK + 2 * i) * SEQ + n],
                       v[((size_t)h * RNK + 2 * i + 1) * SEQ + n]);
    }
    #pragma unroll
    for (int b = 0; b < BATCH; b++) {
        size_t base = ((size_t)(b * HEADS + h) * SEQ + n) * FEAT + 32;
        #pragma unroll
        for (int i = 0; i < 4; i++) {
            *(unsigned*)&g_qa[base + 4 * i]     = uw[i];
            *(unsigned*)&g_ka[base + 4 * i]     = vw[i];
            *(unsigned*)&g_qa[base + 4 * i + 2] = 0u;
            *(unsigned*)&g_ka[base + 4 * i + 2] = 0u;
        }
    }
}

// =============================================================================
// Kernel A1: T = x @ Wql + bql   (8192 x 24). 64 rows/block, 256 threads.
// =============================================================================
#define XSPAD 132
__global__ __launch_bounds__(256) void qkv1_kernel(
    const float* __restrict__ x, const float* __restrict__ Wql,
    const float* __restrict__ bql)
{
    __shared__ float xs[64 * XSPAD];   // ~33.8 KB (pad vs row-bank conflicts)
    __shared__ float ws[HDIM * 24];    // 12 KB

    const int tid  = threadIdx.x;
    const int row0 = blockIdx.x * 64;

    #pragma unroll
    for (int i = 0; i < 8; i++) {
        int e = tid + i * 256, r = e >> 5, c4 = e & 31;
        *(float4*)&xs[r * XSPAD + c4 * 4] =
            ((const float4*)(x + (size_t)row0 * HDIM))[e];
    }
    #pragma unroll
    for (int i = 0; i < 3; i++)
        ((float4*)ws)[tid + i * 256] = ((const float4*)Wql)[tid + i * 256];
    __syncthreads();

    const int r    = tid >> 2;            // 0..63
    const int cgrp = (tid & 3) * 6;       // 0,6,12,18
    float acc[6];
    #pragma unroll
    for (int j = 0; j < 6; j++) acc[j] = bql[cgrp + j];

    #pragma unroll 4
    for (int d = 0; d < HDIM; d++) {
        float xv = xs[r * XSPAD + d];
        float2 w01 = *(const float2*)&ws[d * 24 + cgrp];
        float2 w23 = *(const float2*)&ws[d * 24 + cgrp + 2];
        float2 w45 = *(const float2*)&ws[d * 24 + cgrp + 4];
        acc[0] = fmaf(xv, w01.x, acc[0]);
        acc[1] = fmaf(xv, w01.y, acc[1]);
        acc[2] = fmaf(xv, w23.x, acc[2]);
        acc[3] = fmaf(xv, w23.y, acc[3]);
        acc[4] = fmaf(xv, w45.x, acc[4]);
        acc[5] = fmaf(xv, w45.y, acc[5]);
    }
    float* dst = g_t + (size_t)(row0 + r) * 24 + cgrp;
    *(float2*)(dst + 0) = make_float2(acc[0], acc[1]);
    *(float2*)(dst + 2) = make_float2(acc[2], acc[3]);
    *(float2*)(dst + 4) = make_float2(acc[4], acc[5]);
}

// =============================================================================
// Kernel A2: QKV = T @ Wqh + bqh -> bf16 permuted Q/K + V^T.
// 32 rows x 384 cols per block; Wqh staged once per block. 384 threads.
// =============================================================================
#define TSPAD 28
__global__ __launch_bounds__(384) void qkv2_kernel(
    const float* __restrict__ Wqh, const float* __restrict__ bqh)
{
    __shared__ float wqh[24 * 384];      // 36 KB
    __shared__ float tsm[32 * TSPAD];    // 3.5 KB

    const int tid  = threadIdx.x;
    const int row0 = blockIdx.x * 32;

    #pragma unroll
    for (int i = 0; i < 6; i++)
        ((float4*)wqh)[tid + i * 384] = ((const float4*)Wqh)[tid + i * 384];
    #pragma unroll
    for (int e = tid; e < 32 * 24; e += 384) {
        int rr = e / 24, cc = e - rr * 24;
        tsm[rr * TSPAD + cc] = g_t[(size_t)(row0 + rr) * 24 + cc];
    }
    __syncthreads();

    const int c = tid;                       // 0..383
    float wv[24];
    #pragma unroll
    for (int rk = 0; rk < 24; rk++) wv[rk] = wqh[rk * 384 + c];
    const float bias = bqh[c];

    float acc[32];
    #pragma unroll
    for (int row = 0; row < 32; row++) {
        float a = bias;
        #pragma unroll
        for (int k4 = 0; k4 < 6; k4++) {
            float4 t = *(const float4*)&tsm[row * TSPAD + k4 * 4];
            a = fmaf(t.x, wv[k4 * 4 + 0], a);
            a = fmaf(t.y, wv[k4 * 4 + 1], a);
            a = fmaf(t.z, wv[k4 * 4 + 2], a);
            a = fmaf(t.w, wv[k4 * 4 + 3], a);
        }
        acc[row] = a;
    }

    const int b  = row0 >> 11;
    const int n0 = row0 & (SEQ - 1);
    const int which = c >> 7;
    const int cc = c & 127;
    const int hh = cc >> 5, dd = cc & 31;
    const float qscale = 0.17677669529663687f * LOG2E;   // log2e/sqrt(32)

    if (which < 2) {
        const int fslot = perm16(dd);
        __nv_bfloat16* dst = (which == 0) ? g_qa : g_ka;
        const float sc = (which == 0) ? qscale : 1.0f;
        size_t base = ((size_t)(b * HEADS + hh) * SEQ + n0) * FEAT + fslot;
        #pragma unroll
        for (int row = 0; row < 32; row++)
            dst[base + (size_t)row * FEAT] = __float2bfloat16(acc[row] * sc);
    } else {
        // V^T rows: 32 consecutive n = two permuted 16-groups -> 4 uint4 stores
        size_t base = ((size_t)(b * HEADS + hh) * HD + dd) * SEQ + n0;
        #pragma unroll
        for (int gset = 0; gset < 2; gset++) {
            const float* a = acc + gset * 16;
            uint4 w0, w1;
            w0.x = packbf(a[0],  a[1]);  w0.y = packbf(a[8],  a[9]);
            w0.z = packbf(a[2],  a[3]);  w0.w = packbf(a[10], a[11]);
            w1.x = packbf(a[4],  a[5]);  w1.y = packbf(a[12], a[13]);
            w1.z = packbf(a[6],  a[7]);  w1.w = packbf(a[14], a[15]);
            *(uint4*)&g_vt[base + gset * 16 + 0] = w0;
            *(uint4*)&g_vt[base + gset * 16 + 8] = w1;
        }
    }
}

// =============================================================================
// Kernel B: tensor-core attention. QTILE=64, CHUNK=64, 256 threads, 4 blk/SM.
// All exp inputs pre-scaled by log2e -> single ex2.approx per entry.
// =============================================================================
__global__ __launch_bounds__(256, 4) void attn_kernel()
{
    __shared__ __align__(16) char smem_raw[2 * STAGE_SZ];   // 40 KB

    const int tid  = threadIdx.x;
    const int lane = tid & 31;
    const int warp = tid >> 5;
    const int gid  = lane >> 2;
    const int tig  = lane & 3;
    const int h = blockIdx.y, b = blockIdx.z;
    const int q0 = blockIdx.x * QTILE;
    const int qrow = (warp & 3) * 16;
    const int koff = (warp >> 2) * 32;

    const size_t bh     = (size_t)(b * HEADS + h);
    const size_t krow0  = bh * SEQ;
    const size_t vtrow0 = bh * HD;

    const unsigned sbase = (unsigned)__cvta_generic_to_shared(smem_raw);

    unsigned qa[3][4];
    {
        const __nv_bfloat16* q0p = g_qa + (krow0 + q0 + qrow + gid) * FEAT;
        #pragma unroll
        for (int kk = 0; kk < 3; kk++) {
            uint2 t0 = *(const uint2*)(q0p + 16 * kk + 4 * tig);
            uint2 t1 = *(const uint2*)(q0p + 8 * FEAT + 16 * kk + 4 * tig);
            qa[kk][0] = t0.x; qa[kk][1] = t1.x; qa[kk][2] = t0.y; qa[kk][3] = t1.y;
        }
    }

    float o[4][4];
    #pragma unroll
    for (int i = 0; i < 4; i++)
        #pragma unroll
        for (int j = 0; j < 4; j++) o[i][j] = 0.f;
    float rs0 = 0.f, rs1 = 0.f;

    auto stage = [&](int jc, int s) {
        const int j0 = jc * CHUNK;
        const unsigned kd = sbase + s * STAGE_SZ + K_OFF;
        const unsigned vd = sbase + s * STAGE_SZ + V_OFF;
        const unsigned ad = sbase + s * STAGE_SZ + A_OFF;
        {
            int e = tid, r = e / 6, c = e - r * 6;
            cp16(kd + (r * KPAD + c * 8) * 2, g_ka + (krow0 + j0 + r) * FEAT + c * 8);
            e = tid + 256;
            if (e < 384) {
                r = e / 6; c = e - r * 6;
                cp16(kd + (r * KPAD + c * 8) * 2, g_ka + (krow0 + j0 + r) * FEAT + c * 8);
            }
        }
        {
            int r = tid >> 3, c = tid & 7;
            cp16(vd + (r * VPAD + c * 8) * 2, g_vt + (vtrow0 + r) * SEQ + j0 + c * 8);
        }
        #pragma unroll
        for (int i = 0; i < 2; i++) {
            int e = tid + i * 256, r = e >> 3, c = e & 7;
            cp16(ad + (r * APAD + c * 8) * 2, g_adjb + (size_t)(q0 + r) * SEQ + j0 + c * 8);
        }
    };

    stage(0, 0);
    asm volatile("cp.async.commit_group;");

    for (int jc = 0; jc < NCH; jc++) {
        const int s = jc & 1;
        if (jc + 1 < NCH) {
            stage(jc + 1, s ^ 1);
            asm volatile("cp.async.commit_group;");
            asm volatile("cp.async.wait_group 1;");
        } else {
            asm volatile("cp.async.wait_group 0;");
        }
        __syncthreads();

        const __nv_bfloat16* Ks   = (const __nv_bfloat16*)(smem_raw + s * STAGE_SZ + K_OFF);
        const __nv_bfloat16* Vts  = (const __nv_bfloat16*)(smem_raw + s * STAGE_SZ + V_OFF);
        const __nv_bfloat16* Adjs = (const __nv_bfloat16*)(smem_raw + s * STAGE_SZ + A_OFF);

        #pragma unroll
        for (int gl = 0; gl < 2; gl++) {
            unsigned pa[4];
            #pragma unroll
            for (int t = 0; t < 2; t++) {
                const int kr = koff + gl * 16 + t * 8;
                float c0 = 0.f, c1 = 0.f, c2 = 0.f, c3 = 0.f;
                #pragma unroll
                for (int kk = 0; kk < 3; kk++) {
                    uint2 bb = *(const uint2*)&Ks[(kr + gid) * KPAD + 16 * kk + 4 * tig];
                    mma16816(c0, c1, c2, c3,
                             qa[kk][0], qa[kk][1], qa[kk][2], qa[kk][3], bb.x, bb.y);
                }
                unsigned au0 = *(const unsigned*)&Adjs[(qrow + gid) * APAD + kr + 2 * tig];
                unsigned au1 = *(const unsigned*)&Adjs[(qrow + gid + 8) * APAD + kr + 2 * tig];
                c0 = ex2f(c0 + bflo(au0));
                c1 = ex2f(c1 + bfhi(au0));
                c2 = ex2f(c2 + bflo(au1));
                c3 = ex2f(c3 + bfhi(au1));
                rs0 += c0 + c1;
                rs1 += c2 + c3;
                pa[2 * t]     = packbf(c0, c1);
                pa[2 * t + 1] = packbf(c2, c3);
            }
            #pragma unroll
            for (int nf = 0; nf < 4; nf++) {
                uint2 bb = *(const uint2*)&Vts[(8 * nf + gid) * VPAD + koff + 16 * gl + 4 * tig];
                mma16816(o[nf][0], o[nf][1], o[nf][2], o[nf][3],
                         pa[0], pa[1], pa[2], pa[3], bb.x, bb.y);
            }
        }
        __syncthreads();
    }

    rs0 += __shfl_xor_sync(0xffffffffu, rs0, 1);
    rs0 += __shfl_xor_sync(0xffffffffu, rs0, 2);
    rs1 += __shfl_xor_sync(0xffffffffu, rs1, 1);
    rs1 += __shfl_xor_sync(0xffffffffu, rs1, 2);

    // cross-warp (key-half) combine — alias scratch onto stage-0 buffers
    float* OsumS = (float*)smem_raw;               // [64][33]
    float* rsS   = (float*)(smem_raw + 8448);
    const int orow_l = qrow + gid;

    if (warp >= 4) {
        #pragma unroll
        for (int nf = 0; nf < 4; nf++) {
            OsumS[orow_l * 33 + 8 * nf + 2 * tig]           = o[nf][0];
            OsumS[orow_l * 33 + 8 * nf + 2 * tig + 1]       = o[nf][1];
            OsumS[(orow_l + 8) * 33 + 8 * nf + 2 * tig]     = o[nf][2];
            OsumS[(orow_l + 8) * 33 + 8 * nf + 2 * tig + 1] = o[nf][3];
        }
        if (tig == 0) { rsS[orow_l] = rs0; rsS[orow_l + 8] = rs1; }
    }
    __syncthreads();
    if (warp < 4) {
        #pragma unroll
        for (int nf = 0; nf < 4; nf++) {
            o[nf][0] += OsumS[orow_l * 33 + 8 * nf + 2 * tig];
            o[nf][1] += OsumS[orow_l * 33 + 8 * nf + 2 * tig + 1];
            o[nf][2] += OsumS[(orow_l + 8) * 33 + 8 * nf + 2 * tig];
            o[nf][3] += OsumS[(orow_l + 8) * 33 + 8 * nf + 2 * tig + 1];
        }
        rs0 += rsS[orow_l];
        rs1 += rsS[orow_l + 8];
        const float i0 = 1.f / rs0, i1 = 1.f / rs1;
        const size_t orow = bh * SEQ + q0 + orow_l;
        #pragma unroll
        for (int nf = 0; nf < 4; nf++) {
            *(float2*)&g_o[orow * HD + 8 * nf + 2 * tig] =
                make_float2(o[nf][0] * i0, o[nf][1] * i0);
            *(float2*)&g_o[(orow + 8) * HD + 8 * nf + 2 * tig] =
                make_float2(o[nf][2] * i1, o[nf][3] * i1);
        }
    }
}

// =============================================================================
// Kernel C: output projection + residual + LayerNorm + analytic reg_loss
// =============================================================================
__device__ __forceinline__ float block_sum_128(float val, float* red4) {
    #pragma unroll
    for (int off = 16; off > 0; off >>= 1)
        val += __shfl_xor_sync(0xffffffffu, val, off);
    const int w = threadIdx.x >> 5;
    if ((threadIdx.x & 31) == 0) red4[w] = val;
    __syncthreads();
    val = red4[0] + red4[1] + red4[2] + red4[3];
    __syncthreads();
    return val;
}

__global__ __launch_bounds__(128) void epi_kernel(
    const float* __restrict__ x, const float* __restrict__ Wol,
    const float* __restrict__ bol, const float* __restrict__ Woh,
    const float* __restrict__ boh, const float* __restrict__ gamma,
    const float* __restrict__ beta, const float* __restrict__ log_reg_w,
    float* __restrict__ out, int out_size)
{
    __shared__ float sm[4][8];
    __shared__ float t8[8];
    __shared__ float red4[4];

    const int row = blockIdx.x;
    const int d   = threadIdx.x;
    const int b   = row >> 11;
    const int n   = row & (SEQ - 1);
    const int h   = d >> 5, dd = d & 31;
    const int w   = d >> 5, lane = d & 31;

    const float o_d = g_o[(((size_t)(b * HEADS + h)) * SEQ + n) * HD + dd];

    float w8[8];
    {
        const float4* wp = (const float4*)(Wol + d * RNK);
        float4 t0 = wp[0], t1 = wp[1];
        w8[0] = t0.x; w8[1] = t0.y; w8[2] = t0.z; w8[3] = t0.w;
        w8[4] = t1.x; w8[5] = t1.y; w8[6] = t1.z; w8[7] = t1.w;
    }
    #pragma unroll
    for (int r = 0; r < 8; r++) {
        float p = o_d * w8[r];
        #pragma unroll
        for (int off = 16; off > 0; off >>= 1)
            p += __shfl_xor_sync(0xffffffffu, p, off);
        if (lane == 0) sm[w][r] = p;
    }
    __syncthreads();
    if (d < 8) t8[d] = sm[0][d] + sm[1][d] + sm[2][d] + sm[3][d] + bol[d];
    __syncthreads();

    float o2 = boh[d];
    #pragma unroll
    for (int r = 0; r < 8; r++) o2 = fmaf(t8[r], Woh[r * HDIM + d], o2);
    float y = o2 + x[(size_t)row * HDIM + d];

    float mu = block_sum_128(y, red4) * (1.0f / HDIM);
    float dy = y - mu;
    float var = block_sum_128(dy * dy, red4) * (1.0f / HDIM);
    float res = dy * rsqrtf(var + 1e-5f) * gamma[d] + beta[d];
    out[(size_t)row * HDIM + d] = res;

    if (row == 0 && d == 0) {
        float reg = expf(log_reg_w[0]) * (1.0f / (float)SEQ);
        for (int i = NTOT; i < out_size; i++) out[i] = reg;
    }
}

// =============================================================================
extern "C" void kernel_launch(void* const* d_in, const int* in_sizes, int n_in,
                              void* d_out, int out_size)
{
    const float* x         = (const float*)d_in[0];
    const float* Wql       = (const float*)d_in[1];
    const float* bql       = (const float*)d_in[2];
    const float* Wqh       = (const float*)d_in[3];
    const float* bqh       = (const float*)d_in[4];
    const float* u         = (const float*)d_in[5];
    const float* v         = (const float*)d_in[6];
    const float* adj_scale = (const float*)d_in[7];
    const float* Wol       = (const float*)d_in[8];
    const float* bol       = (const float*)d_in[9];
    const float* Woh       = (const float*)d_in[10];
    const float* boh       = (const float*)d_in[11];
    const float* gamma     = (const float*)d_in[12];
    const float* beta      = (const float*)d_in[13];
    const float* log_reg_w = (const float*)d_in[14];
    const float* adj_prior = (const float*)d_in[15];
    float* out = (float*)d_out;

    adjcvt_kernel<<<(SEQ * SEQ) / (8 * 256), 256>>>(adj_prior, adj_scale);
    aug_kernel<<<(HEADS * SEQ + 255) / 256, 256>>>(u, v);
    qkv1_kernel<<<(BATCH * SEQ) / 64, 256>>>(x, Wql, bql);
    qkv2_kernel<<<(BATCH * SEQ) / 32, 384>>>(Wqh, bqh);
    attn_kernel<<<dim3(SEQ / QTILE, HEADS, BATCH), 256>>>();
    epi_kernel<<<BATCH * SEQ, 128>>>(x, Wol, bol, Woh, boh, gamma, beta,
                                     log_reg_w, out, out_size);
}

// round 6
// speedup vs baseline: 1.4322x; 1.0429x over previous
#include <cuda_runtime.h>
#include <cuda_bf16.h>
#include <math.h>

#define BATCH 4
#define SEQ   2048
#define HDIM  128
#define HEADS 4
#define HD    32
#define RNK   8
#define FEAT  48            // 32 (qk) + 8 (u/v bias) + 8 zero pad
#define KPAD  48
#define VPAD  80
#define APAD  72
#define QTILE 128
#define CHUNK 64
#define NCH   (SEQ / CHUNK)
#define NTOT  (BATCH * SEQ * HDIM)
#define LOG2E 1.4426950408889634f

// smem stage layout (bytes)
#define K_OFF    0
#define K_BYTES  (CHUNK * KPAD * 2)            // 6144
#define V_OFF    K_BYTES
#define V_BYTES  (HD * VPAD * 2)               // 5120
#define A_OFF    (V_OFF + V_BYTES)
#define A_BYTES  (QTILE * APAD * 2)            // 18432
#define STAGE_SZ (A_OFF + A_BYTES)             // 29696
#define ATTN_SMEM (2 * STAGE_SZ)               // 59392

// ---------------- static device scratch ------------------------------------
__device__ __align__(16) __nv_bfloat16 g_qa[BATCH * HEADS * SEQ * FEAT];
__device__ __align__(16) __nv_bfloat16 g_ka[BATCH * HEADS * SEQ * FEAT];
__device__ __align__(16) __nv_bfloat16 g_vt[BATCH * HEADS * HD * SEQ];
__device__ __align__(16) __nv_bfloat16 g_adjb[SEQ * SEQ];    // pre-scaled softplus*log2e
__device__ __align__(16) float         g_o[BATCH * HEADS * SEQ * HD];
__device__ __align__(16) float         g_t[BATCH * SEQ * 24];

// ---------------- helpers ---------------------------------------------------
__device__ __forceinline__ unsigned packbf(float lo, float hi) {
    unsigned r;
    asm("cvt.rn.bf16x2.f32 %0, %1, %2;" : "=r"(r) : "f"(hi), "f"(lo));
    return r;
}
__device__ __forceinline__ float bflo(unsigned u) { return __int_as_float(u << 16); }
__device__ __forceinline__ float bfhi(unsigned u) { return __int_as_float(u & 0xffff0000u); }
__device__ __forceinline__ float ex2f(float x) {
    float y;
    asm("ex2.approx.f32 %0, %1;" : "=f"(y) : "f"(x));
    return y;
}

__device__ __host__ __forceinline__ int perm16(int c) {
    int g = c & ~15, c16 = c & 15;
    return g + 4 * ((c16 >> 1) & 3) + 2 * (c16 >> 3) + (c16 & 1);
}

__device__ __forceinline__ void mma16816(float& c0, float& c1, float& c2, float& c3,
                                         unsigned a0, unsigned a1, unsigned a2, unsigned a3,
                                         unsigned b0, unsigned b1) {
    asm volatile("mma.sync.aligned.m16n8k16.row.col.f32.bf16.bf16.f32 "
                 "{%0,%1,%2,%3}, {%4,%5,%6,%7}, {%8,%9}, {%0,%1,%2,%3};"
                 : "+f"(c0), "+f"(c1), "+f"(c2), "+f"(c3)
                 : "r"(a0), "r"(a1), "r"(a2), "r"(a3), "r"(b0), "r"(b1));
}

__device__ __forceinline__ void cp16(unsigned smem_dst, const void* gsrc) {
    asm volatile("cp.async.cg.shared.global [%0], [%1], 16;" :: "r"(smem_dst), "l"(gsrc));
}

// =============================================================================
// Prologue 1: adj fp32 -> bf16, pre-multiplied by softplus(adj_scale)*log2e
// =============================================================================
__global__ __launch_bounds__(256) void adjcvt_kernel(const float* __restrict__ adj,
                                                     const float* __restrict__ adj_scale) {
    const float cs = log1pf(expf(adj_scale[0])) * LOG2E;
    int i = blockIdx.x * 256 + threadIdx.x;
    const float4* src = (const float4*)adj + (size_t)i * 2;
    float4 f0 = src[0], f1 = src[1];
    uint4 d;
    d.x = packbf(f0.x * cs, f0.y * cs);
    d.y = packbf(f0.z * cs, f0.w * cs);
    d.z = packbf(f1.x * cs, f1.y * cs);
    d.w = packbf(f1.z * cs, f1.w * cs);
    ((uint4*)g_adjb)[i] = d;
}

// =============================================================================
// Prologue 2: u*log2e -> Q-aug cols 32..47, v -> K-aug cols 32..47 (permuted)
// =============================================================================
__global__ __launch_bounds__(256) void aug_kernel(const float* __restrict__ u,
                                                  const float* __restrict__ v) {
    int idx = blockIdx.x * 256 + threadIdx.x;
    if (idx >= HEADS * SEQ) return;
    int h = idx >> 11, n = idx & (SEQ - 1);
    unsigned uw[4], vw[4];
    #pragma unroll
    for (int i = 0; i < 4; i++) {
        uw[i] = packbf(u[((size_t)h * SEQ + n) * RNK + 2 * i] * LOG2E,
                       u[((size_t)h * SEQ + n) * RNK + 2 * i + 1] * LOG2E);
        vw[i] = packbf(v[((size_t)h * RNK + 2 * i) * SEQ + n],
                       v[((size_t)h * RNK + 2 * i + 1) * SEQ + n]);
    }
    #pragma unroll
    for (int b = 0; b < BATCH; b++) {
        size_t base = ((size_t)(b * HEADS + h) * SEQ + n) * FEAT + 32;
        #pragma unroll
        for (int i = 0; i < 4; i++) {
            *(unsigned*)&g_qa[base + 4 * i]     = uw[i];
            *(unsigned*)&g_ka[base + 4 * i]     = vw[i];
            *(unsigned*)&g_qa[base + 4 * i + 2] = 0u;
            *(unsigned*)&g_ka[base + 4 * i + 2] = 0u;
        }
    }
}

// =============================================================================
// Kernel A1: T = x @ Wql + bql   (8192 x 24). 64 rows/block, 256 threads.
// =============================================================================
#define XSPAD 132
__global__ __launch_bounds__(256) void qkv1_kernel(
    const float* __restrict__ x, const float* __restrict__ Wql,
    const float* __restrict__ bql)
{
    __shared__ float xs[64 * XSPAD];
    __shared__ float ws[HDIM * 24];

    const int tid  = threadIdx.x;
    const int row0 = blockIdx.x * 64;

    #pragma unroll
    for (int i = 0; i < 8; i++) {
        int e = tid + i * 256, r = e >> 5, c4 = e & 31;
        *(float4*)&xs[r * XSPAD + c4 * 4] =
            ((const float4*)(x + (size_t)row0 * HDIM))[e];
    }
    #pragma unroll
    for (int i = 0; i < 3; i++)
        ((float4*)ws)[tid + i * 256] = ((const float4*)Wql)[tid + i * 256];
    __syncthreads();

    const int r    = tid >> 2;
    const int cgrp = (tid & 3) * 6;
    float acc[6];
    #pragma unroll
    for (int j = 0; j < 6; j++) acc[j] = bql[cgrp + j];

    #pragma unroll 4
    for (int d = 0; d < HDIM; d++) {
        float xv = xs[r * XSPAD + d];
        float2 w01 = *(const float2*)&ws[d * 24 + cgrp];
        float2 w23 = *(const float2*)&ws[d * 24 + cgrp + 2];
        float2 w45 = *(const float2*)&ws[d * 24 + cgrp + 4];
        acc[0] = fmaf(xv, w01.x, acc[0]);
        acc[1] = fmaf(xv, w01.y, acc[1]);
        acc[2] = fmaf(xv, w23.x, acc[2]);
        acc[3] = fmaf(xv, w23.y, acc[3]);
        acc[4] = fmaf(xv, w45.x, acc[4]);
        acc[5] = fmaf(xv, w45.y, acc[5]);
    }
    float* dst = g_t + (size_t)(row0 + r) * 24 + cgrp;
    *(float2*)(dst + 0) = make_float2(acc[0], acc[1]);
    *(float2*)(dst + 2) = make_float2(acc[2], acc[3]);
    *(float2*)(dst + 4) = make_float2(acc[4], acc[5]);
}

// =============================================================================
// Kernel A2: QKV = T @ Wqh + bqh -> bf16 permuted Q/K + V^T.
// 16 rows x 384 cols per block (grid 512); Wqh staged once. 384 threads.
// =============================================================================
#define ROWS2 16
#define TSPAD 28
__global__ __launch_bounds__(384) void qkv2_kernel(
    const float* __restrict__ Wqh, const float* __restrict__ bqh)
{
    __shared__ float wqh[24 * 384];        // 36 KB
    __shared__ float tsm[ROWS2 * TSPAD];   // 1.75 KB

    const int tid  = threadIdx.x;
    const int row0 = blockIdx.x * ROWS2;

    #pragma unroll
    for (int i = 0; i < 6; i++)
        ((float4*)wqh)[tid + i * 384] = ((const float4*)Wqh)[tid + i * 384];
    for (int e = tid; e < ROWS2 * 24; e += 384) {
        int rr = e / 24, cc = e - rr * 24;
        tsm[rr * TSPAD + cc] = g_t[(size_t)(row0 + rr) * 24 + cc];
    }
    __syncthreads();

    const int c = tid;
    float wv[24];
    #pragma unroll
    for (int rk = 0; rk < 24; rk++) wv[rk] = wqh[rk * 384 + c];
    const float bias = bqh[c];

    float acc[ROWS2];
    #pragma unroll
    for (int row = 0; row < ROWS2; row++) {
        float a = bias;
        #pragma unroll
        for (int k4 = 0; k4 < 6; k4++) {
            float4 t = *(const float4*)&tsm[row * TSPAD + k4 * 4];
            a = fmaf(t.x, wv[k4 * 4 + 0], a);
            a = fmaf(t.y, wv[k4 * 4 + 1], a);
            a = fmaf(t.z, wv[k4 * 4 + 2], a);
            a = fmaf(t.w, wv[k4 * 4 + 3], a);
        }
        acc[row] = a;
    }

    const int b  = row0 >> 11;
    const int n0 = row0 & (SEQ - 1);
    const int which = c >> 7;
    const int cc = c & 127;
    const int hh = cc >> 5, dd = cc & 31;
    const float qscale = 0.17677669529663687f * LOG2E;

    if (which < 2) {
        const int fslot = perm16(dd);
        __nv_bfloat16* dst = (which == 0) ? g_qa : g_ka;
        const float sc = (which == 0) ? qscale : 1.0f;
        size_t base = ((size_t)(b * HEADS + hh) * SEQ + n0) * FEAT + fslot;
        #pragma unroll
        for (int row = 0; row < ROWS2; row++)
            dst[base + (size_t)row * FEAT] = __float2bfloat16(acc[row] * sc);
    } else {
        // V^T: 16 consecutive n = one permuted 16-group -> 2 uint4 stores
        size_t base = ((size_t)(b * HEADS + hh) * HD + dd) * SEQ + n0;
        uint4 w0, w1;
        w0.x = packbf(acc[0],  acc[1]);  w0.y = packbf(acc[8],  acc[9]);
        w0.z = packbf(acc[2],  acc[3]);  w0.w = packbf(acc[10], acc[11]);
        w1.x = packbf(acc[4],  acc[5]);  w1.y = packbf(acc[12], acc[13]);
        w1.z = packbf(acc[6],  acc[7]);  w1.w = packbf(acc[14], acc[15]);
        *(uint4*)&g_vt[base + 0] = w0;
        *(uint4*)&g_vt[base + 8] = w1;
    }
}

// =============================================================================
// Kernel B: tensor-core attention. QTILE=128, CHUNK=64, 256 threads.
// 8 warps = 8 q-subtiles; each warp processes ALL 64 chunk keys (no combine).
// Dynamic smem, double-buffered cp.async staging.
// =============================================================================
__global__ __launch_bounds__(256, 3) void attn_kernel()
{
    extern __shared__ __align__(16) char smem_raw[];

    const int tid  = threadIdx.x;
    const int lane = tid & 31;
    const int warp = tid >> 5;
    const int gid  = lane >> 2;
    const int tig  = lane & 3;
    const int h = blockIdx.y, b = blockIdx.z;
    const int q0 = blockIdx.x * QTILE;
    const int qrow = warp * 16;

    const size_t bh     = (size_t)(b * HEADS + h);
    const size_t krow0  = bh * SEQ;
    const size_t vtrow0 = bh * HD;

    const unsigned sbase = (unsigned)__cvta_generic_to_shared(smem_raw);

    unsigned qa[3][4];
    {
        const __nv_bfloat16* q0p = g_qa + (krow0 + q0 + qrow + gid) * FEAT;
        #pragma unroll
        for (int kk = 0; kk < 3; kk++) {
            uint2 t0 = *(const uint2*)(q0p + 16 * kk + 4 * tig);
            uint2 t1 = *(const uint2*)(q0p + 8 * FEAT + 16 * kk + 4 * tig);
            qa[kk][0] = t0.x; qa[kk][1] = t1.x; qa[kk][2] = t0.y; qa[kk][3] = t1.y;
        }
    }

    float o[4][4];
    #pragma unroll
    for (int i = 0; i < 4; i++)
        #pragma unroll
        for (int j = 0; j < 4; j++) o[i][j] = 0.f;
    float rs0 = 0.f, rs1 = 0.f;

    auto stage = [&](int jc, int s) {
        const int j0 = jc * CHUNK;
        const unsigned kd = sbase + s * STAGE_SZ + K_OFF;
        const unsigned vd = sbase + s * STAGE_SZ + V_OFF;
        const unsigned ad = sbase + s * STAGE_SZ + A_OFF;
        {   // K: 64 x 48 el = 384 uint4
            int e = tid, r = e / 6, c = e - r * 6;
            cp16(kd + (r * KPAD + c * 8) * 2, g_ka + (krow0 + j0 + r) * FEAT + c * 8);
            e = tid + 256;
            if (e < 384) {
                r = e / 6; c = e - r * 6;
                cp16(kd + (r * KPAD + c * 8) * 2, g_ka + (krow0 + j0 + r) * FEAT + c * 8);
            }
        }
        {   // V^T: 32 x 64 el = 256 uint4
            int r = tid >> 3, c = tid & 7;
            cp16(vd + (r * VPAD + c * 8) * 2, g_vt + (vtrow0 + r) * SEQ + j0 + c * 8);
        }
        #pragma unroll
        for (int i = 0; i < 4; i++) {   // adj: 128 x 64 el = 1024 uint4
            int e = tid + i * 256, r = e >> 3, c = e & 7;
            cp16(ad + (r * APAD + c * 8) * 2, g_adjb + (size_t)(q0 + r) * SEQ + j0 + c * 8);
        }
    };

    stage(0, 0);
    asm volatile("cp.async.commit_group;");

    for (int jc = 0; jc < NCH; jc++) {
        const int s = jc & 1;
        if (jc + 1 < NCH) {
            stage(jc + 1, s ^ 1);
            asm volatile("cp.async.commit_group;");
            asm volatile("cp.async.wait_group 1;");
        } else {
            asm volatile("cp.async.wait_group 0;");
        }
        __syncthreads();

        const __nv_bfloat16* Ks   = (const __nv_bfloat16*)(smem_raw + s * STAGE_SZ + K_OFF);
        const __nv_bfloat16* Vts  = (const __nv_bfloat16*)(smem_raw + s * STAGE_SZ + V_OFF);
        const __nv_bfloat16* Adjs = (const __nv_bfloat16*)(smem_raw + s * STAGE_SZ + A_OFF);

        #pragma unroll
        for (int gl = 0; gl < 4; gl++) {       // 16 keys per gl, 64 total
            unsigned pa[4];
            #pragma unroll
            for (int t = 0; t < 2; t++) {
                const int kr = gl * 16 + t * 8;
                float c0 = 0.f, c1 = 0.f, c2 = 0.f, c3 = 0.f;
                #pragma unroll
                for (int kk = 0; kk < 3; kk++) {
                    uint2 bb = *(const uint2*)&Ks[(kr + gid) * KPAD + 16 * kk + 4 * tig];
                    mma16816(c0, c1, c2, c3,
                             qa[kk][0], qa[kk][1], qa[kk][2], qa[kk][3], bb.x, bb.y);
                }
                unsigned au0 = *(const unsigned*)&Adjs[(qrow + gid) * APAD + kr + 2 * tig];
                unsigned au1 = *(const unsigned*)&Adjs[(qrow + gid + 8) * APAD + kr + 2 * tig];
                c0 = ex2f(c0 + bflo(au0));
                c1 = ex2f(c1 + bfhi(au0));
                c2 = ex2f(c2 + bflo(au1));
                c3 = ex2f(c3 + bfhi(au1));
                rs0 += c0 + c1;
                rs1 += c2 + c3;
                pa[2 * t]     = packbf(c0, c1);
                pa[2 * t + 1] = packbf(c2, c3);
            }
            #pragma unroll
            for (int nf = 0; nf < 4; nf++) {
                uint2 bb = *(const uint2*)&Vts[(8 * nf + gid) * VPAD + 16 * gl + 4 * tig];
                mma16816(o[nf][0], o[nf][1], o[nf][2], o[nf][3],
                         pa[0], pa[1], pa[2], pa[3], bb.x, bb.y);
            }
        }
        __syncthreads();
    }

    // quad-reduce row sums, normalize, store (no cross-warp combine needed)
    rs0 += __shfl_xor_sync(0xffffffffu, rs0, 1);
    rs0 += __shfl_xor_sync(0xffffffffu, rs0, 2);
    rs1 += __shfl_xor_sync(0xffffffffu, rs1, 1);
    rs1 += __shfl_xor_sync(0xffffffffu, rs1, 2);
    const float i0 = 1.f / rs0, i1 = 1.f / rs1;

    const size_t orow = bh * SEQ + q0 + qrow + gid;
    #pragma unroll
    for (int nf = 0; nf < 4; nf++) {
        *(float2*)&g_o[orow * HD + 8 * nf + 2 * tig] =
            make_float2(o[nf][0] * i0, o[nf][1] * i0);
        *(float2*)&g_o[(orow + 8) * HD + 8 * nf + 2 * tig] =
            make_float2(o[nf][2] * i1, o[nf][3] * i1);
    }
}

// =============================================================================
// Kernel C: warp-per-row output projection + residual + LayerNorm + reg tail.
// 8 warps/block = 8 rows; all reductions via shuffles; zero __syncthreads.
// =============================================================================
__global__ __launch_bounds__(256) void epi_kernel(
    const float* __restrict__ x, const float* __restrict__ Wol,
    const float* __restrict__ bol, const float* __restrict__ Woh,
    const float* __restrict__ boh, const float* __restrict__ gamma,
    const float* __restrict__ beta, const float* __restrict__ log_reg_w,
    float* __restrict__ out, int out_size)
{
    const int warp = threadIdx.x >> 5;
    const int lane = threadIdx.x & 31;
    const int row  = blockIdx.x * 8 + warp;
    const int b    = row >> 11;
    const int n    = row & (SEQ - 1);

    // lane handles dims d = lane + 32*i, i=0..3 (i is also the head index)
    float ov[4];
    #pragma unroll
    for (int i = 0; i < 4; i++)
        ov[i] = g_o[(((size_t)(b * HEADS + i)) * SEQ + n) * HD + lane];

    // t[r] = sum_d o_d * Wol[d][r] + bol[r]
    float t8[8];
    #pragma unroll
    for (int r = 0; r < 8; r++) t8[r] = 0.f;
    #pragma unroll
    for (int i = 0; i < 4; i++) {
        const int d = lane + 32 * i;
        const float4* wp = (const float4*)(Wol + d * RNK);
        float4 w0 = wp[0], w1 = wp[1];
        t8[0] = fmaf(ov[i], w0.x, t8[0]);
        t8[1] = fmaf(ov[i], w0.y, t8[1]);
        t8[2] = fmaf(ov[i], w0.z, t8[2]);
        t8[3] = fmaf(ov[i], w0.w, t8[3]);
        t8[4] = fmaf(ov[i], w1.x, t8[4]);
        t8[5] = fmaf(ov[i], w1.y, t8[5]);
        t8[6] = fmaf(ov[i], w1.z, t8[6]);
        t8[7] = fmaf(ov[i], w1.w, t8[7]);
    }
    #pragma unroll
    for (int r = 0; r < 8; r++) {
        #pragma unroll
        for (int off = 16; off > 0; off >>= 1)
            t8[r] += __shfl_xor_sync(0xffffffffu, t8[r], off);
        t8[r] += bol[r];
    }

    // y_d = t @ Woh[:,d] + boh_d + x_d  for this lane's 4 dims
    float y[4];
    #pragma unroll
    for (int i = 0; i < 4; i++) {
        const int d = lane + 32 * i;
        float o2 = boh[d];
        #pragma unroll
        for (int r = 0; r < 8; r++) o2 = fmaf(t8[r], Woh[r * HDIM + d], o2);
        y[i] = o2 + x[(size_t)row * HDIM + d];
    }

    float s = y[0] + y[1] + y[2] + y[3];
    #pragma unroll
    for (int off = 16; off > 0; off >>= 1)
        s += __shfl_xor_sync(0xffffffffu, s, off);
    const float mu = s * (1.0f / HDIM);

    float v = 0.f;
    #pragma unroll
    for (int i = 0; i < 4; i++) { y[i] -= mu; v = fmaf(y[i], y[i], v); }
    #pragma unroll
    for (int off = 16; off > 0; off >>= 1)
        v += __shfl_xor_sync(0xffffffffu, v, off);
    const float rstd = rsqrtf(v * (1.0f / HDIM) + 1e-5f);

    #pragma unroll
    for (int i = 0; i < 4; i++) {
        const int d = lane + 32 * i;
        out[(size_t)row * HDIM + d] = y[i] * rstd * gamma[d] + beta[d];
    }

    if (row == 0 && lane == 0) {
        float reg = expf(log_reg_w[0]) * (1.0f / (float)SEQ);
        for (int i = NTOT; i < out_size; i++) out[i] = reg;
    }
}

// =============================================================================
extern "C" void kernel_launch(void* const* d_in, const int* in_sizes, int n_in,
                              void* d_out, int out_size)
{
    const float* x         = (const float*)d_in[0];
    const float* Wql       = (const float*)d_in[1];
    const float* bql       = (const float*)d_in[2];
    const float* Wqh       = (const float*)d_in[3];
    const float* bqh       = (const float*)d_in[4];
    const float* u         = (const float*)d_in[5];
    const float* v         = (const float*)d_in[6];
    const float* adj_scale = (const float*)d_in[7];
    const float* Wol       = (const float*)d_in[8];
    const float* bol       = (const float*)d_in[9];
    const float* Woh       = (const float*)d_in[10];
    const float* boh       = (const float*)d_in[11];
    const float* gamma     = (const float*)d_in[12];
    const float* beta      = (const float*)d_in[13];
    const float* log_reg_w = (const float*)d_in[14];
    const float* adj_prior = (const float*)d_in[15];
    float* out = (float*)d_out;

    static bool attr_set = false;
    if (!attr_set) {
        cudaFuncSetAttribute(attn_kernel,
                             cudaFuncAttributeMaxDynamicSharedMemorySize, ATTN_SMEM);
        attr_set = true;
    }

    adjcvt_kernel<<<(SEQ * SEQ) / (8 * 256), 256>>>(adj_prior, adj_scale);
    aug_kernel<<<(HEADS * SEQ + 255) / 256, 256>>>(u, v);
    qkv1_kernel<<<(BATCH * SEQ) / 64, 256>>>(x, Wql, bql);
    qkv2_kernel<<<(BATCH * SEQ) / ROWS2, 384>>>(Wqh, bqh);
    attn_kernel<<<dim3(SEQ / QTILE, HEADS, BATCH), 256, ATTN_SMEM>>>();
    epi_kernel<<<(BATCH * SEQ) / 8, 256>>>(x, Wol, bol, Woh, boh, gamma, beta,
                                           log_reg_w, out, out_size);
}

// round 7
// speedup vs baseline: 1.4628x; 1.0214x over previous
#include <cuda_runtime.h>
#include <cuda_bf16.h>
#include <math.h>

#define BATCH 4
#define SEQ   2048
#define HDIM  128
#define HEADS 4
#define HD    32
#define RNK   8
#define FEAT  48            // 32 (qk) + 8 (u/v bias) + 8 zero pad
#define KPAD  48
#define VPAD  80
#define APAD  72
#define QTILE 128
#define CHUNK 64
#define NCH   (SEQ / CHUNK)
#define NTOT  (BATCH * SEQ * HDIM)
#define LOG2E 1.4426950408889634f

// smem stage layout (bytes)
#define K_OFF    0
#define K_BYTES  (CHUNK * KPAD * 2)            // 6144
#define V_OFF    K_BYTES
#define V_BYTES  (HD * VPAD * 2)               // 5120
#define A_OFF    (V_OFF + V_BYTES)
#define A_BYTES  (QTILE * APAD * 2)            // 18432
#define STAGE_SZ (A_OFF + A_BYTES)             // 29696
#define ATTN_SMEM (2 * STAGE_SZ)               // 59392

// ---------------- static device scratch ------------------------------------
__device__ __align__(16) __nv_bfloat16 g_qa[BATCH * HEADS * SEQ * FEAT];
__device__ __align__(16) __nv_bfloat16 g_ka[BATCH * HEADS * SEQ * FEAT];
__device__ __align__(16) __nv_bfloat16 g_vt[BATCH * HEADS * HD * SEQ];
__device__ __align__(16) __nv_bfloat16 g_adjb[SEQ * SEQ];    // pre-scaled softplus*log2e
__device__ __align__(16) float         g_o[BATCH * HEADS * SEQ * HD];
__device__ __align__(16) float         g_t[BATCH * SEQ * 24];

// ---------------- helpers ---------------------------------------------------
__device__ __forceinline__ unsigned packbf(float lo, float hi) {
    unsigned r;
    asm("cvt.rn.bf16x2.f32 %0, %1, %2;" : "=r"(r) : "f"(hi), "f"(lo));
    return r;
}
__device__ __forceinline__ float bflo(unsigned u) { return __int_as_float(u << 16); }
__device__ __forceinline__ float bfhi(unsigned u) { return __int_as_float(u & 0xffff0000u); }
__device__ __forceinline__ float ex2f(float x) {
    float y;
    asm("ex2.approx.f32 %0, %1;" : "=f"(y) : "f"(x));
    return y;
}

__device__ __host__ __forceinline__ int perm16(int c) {
    int g = c & ~15, c16 = c & 15;
    return g + 4 * ((c16 >> 1) & 3) + 2 * (c16 >> 3) + (c16 & 1);
}

__device__ __forceinline__ void mma16816(float& c0, float& c1, float& c2, float& c3,
                                         unsigned a0, unsigned a1, unsigned a2, unsigned a3,
                                         unsigned b0, unsigned b1) {
    asm volatile("mma.sync.aligned.m16n8k16.row.col.f32.bf16.bf16.f32 "
                 "{%0,%1,%2,%3}, {%4,%5,%6,%7}, {%8,%9}, {%0,%1,%2,%3};"
                 : "+f"(c0), "+f"(c1), "+f"(c2), "+f"(c3)
                 : "r"(a0), "r"(a1), "r"(a2), "r"(a3), "r"(b0), "r"(b1));
}

__device__ __forceinline__ void cp16(unsigned smem_dst, const void* gsrc) {
    asm volatile("cp.async.cg.shared.global [%0], [%1], 16;" :: "r"(smem_dst), "l"(gsrc));
}

// =============================================================================
// Prologue 1: adj fp32 -> bf16, pre-multiplied by softplus(adj_scale)*log2e
// =============================================================================
__global__ __launch_bounds__(256) void adjcvt_kernel(const float* __restrict__ adj,
                                                     const float* __restrict__ adj_scale) {
    const float cs = log1pf(expf(adj_scale[0])) * LOG2E;
    int i = blockIdx.x * 256 + threadIdx.x;
    const float4* src = (const float4*)adj + (size_t)i * 2;
    float4 f0 = src[0], f1 = src[1];
    uint4 d;
    d.x = packbf(f0.x * cs, f0.y * cs);
    d.y = packbf(f0.z * cs, f0.w * cs);
    d.z = packbf(f1.x * cs, f1.y * cs);
    d.w = packbf(f1.z * cs, f1.w * cs);
    ((uint4*)g_adjb)[i] = d;
}

// =============================================================================
// Prologue 2: u*log2e -> Q-aug cols 32..47, v -> K-aug cols 32..47 (permuted)
// =============================================================================
__global__ __launch_bounds__(256) void aug_kernel(const float* __restrict__ u,
                                                  const float* __restrict__ v) {
    int idx = blockIdx.x * 256 + threadIdx.x;
    if (idx >= HEADS * SEQ) return;
    int h = idx >> 11, n = idx & (SEQ - 1);
    unsigned uw[4], vw[4];
    #pragma unroll
    for (int i = 0; i < 4; i++) {
        uw[i] = packbf(u[((size_t)h * SEQ + n) * RNK + 2 * i] * LOG2E,
                       u[((size_t)h * SEQ + n) * RNK + 2 * i + 1] * LOG2E);
        vw[i] = packbf(v[((size_t)h * RNK + 2 * i) * SEQ + n],
                       v[((size_t)h * RNK + 2 * i + 1) * SEQ + n]);
    }
    #pragma unroll
    for (int b = 0; b < BATCH; b++) {
        size_t base = ((size_t)(b * HEADS + h) * SEQ + n) * FEAT + 32;
        #pragma unroll
        for (int i = 0; i < 4; i++) {
            *(unsigned*)&g_qa[base + 4 * i]     = uw[i];
            *(unsigned*)&g_ka[base + 4 * i]     = vw[i];
            *(unsigned*)&g_qa[base + 4 * i + 2] = 0u;
            *(unsigned*)&g_ka[base + 4 * i + 2] = 0u;
        }
    }
}

// =============================================================================
// Kernel A1: T = x @ Wql + bql   (8192 x 24). 64 rows/block, 256 threads.
// =============================================================================
#define XSPAD 132
__global__ __launch_bounds__(256) void qkv1_kernel(
    const float* __restrict__ x, const float* __restrict__ Wql,
    const float* __restrict__ bql)
{
    __shared__ float xs[64 * XSPAD];
    __shared__ float ws[HDIM * 24];

    const int tid  = threadIdx.x;
    const int row0 = blockIdx.x * 64;

    #pragma unroll
    for (int i = 0; i < 8; i++) {
        int e = tid + i * 256, r = e >> 5, c4 = e & 31;
        *(float4*)&xs[r * XSPAD + c4 * 4] =
            ((const float4*)(x + (size_t)row0 * HDIM))[e];
    }
    #pragma unroll
    for (int i = 0; i < 3; i++)
        ((float4*)ws)[tid + i * 256] = ((const float4*)Wql)[tid + i * 256];
    __syncthreads();

    const int r    = tid >> 2;
    const int cgrp = (tid & 3) * 6;
    float acc[6];
    #pragma unroll
    for (int j = 0; j < 6; j++) acc[j] = bql[cgrp + j];

    #pragma unroll 4
    for (int d = 0; d < HDIM; d++) {
        float xv = xs[r * XSPAD + d];
        float2 w01 = *(const float2*)&ws[d * 24 + cgrp];
        float2 w23 = *(const float2*)&ws[d * 24 + cgrp + 2];
        float2 w45 = *(const float2*)&ws[d * 24 + cgrp + 4];
        acc[0] = fmaf(xv, w01.x, acc[0]);
        acc[1] = fmaf(xv, w01.y, acc[1]);
        acc[2] = fmaf(xv, w23.x, acc[2]);
        acc[3] = fmaf(xv, w23.y, acc[3]);
        acc[4] = fmaf(xv, w45.x, acc[4]);
        acc[5] = fmaf(xv, w45.y, acc[5]);
    }
    float* dst = g_t + (size_t)(row0 + r) * 24 + cgrp;
    *(float2*)(dst + 0) = make_float2(acc[0], acc[1]);
    *(float2*)(dst + 2) = make_float2(acc[2], acc[3]);
    *(float2*)(dst + 4) = make_float2(acc[4], acc[5]);
}

// =============================================================================
// Kernel A2: QKV = T @ Wqh + bqh -> bf16 permuted Q/K + V^T.
// 384 threads = one output column each; Wqh held in REGISTERS (no smem stage).
// 32 rows per block (grid 256).
// =============================================================================
#define ROWS2 32
#define TSPAD 28
__global__ __launch_bounds__(384) void qkv2_kernel(
    const float* __restrict__ Wqh, const float* __restrict__ bqh)
{
    __shared__ float tsm[ROWS2 * TSPAD];   // 3.5 KB

    const int tid  = threadIdx.x;
    const int row0 = blockIdx.x * ROWS2;
    const int c = tid;

    // per-thread column weights straight from global (coalesced, L2-hot)
    float wv[24];
    #pragma unroll
    for (int rk = 0; rk < 24; rk++) wv[rk] = __ldg(&Wqh[rk * 384 + c]);
    const float bias = __ldg(&bqh[c]);

    for (int e = tid; e < ROWS2 * 24; e += 384) {
        int rr = e / 24, cc = e - rr * 24;
        tsm[rr * TSPAD + cc] = g_t[(size_t)(row0 + rr) * 24 + cc];
    }
    __syncthreads();

    float acc[ROWS2];
    #pragma unroll
    for (int row = 0; row < ROWS2; row++) {
        float a = bias;
        #pragma unroll
        for (int k4 = 0; k4 < 6; k4++) {
            float4 t = *(const float4*)&tsm[row * TSPAD + k4 * 4];
            a = fmaf(t.x, wv[k4 * 4 + 0], a);
            a = fmaf(t.y, wv[k4 * 4 + 1], a);
            a = fmaf(t.z, wv[k4 * 4 + 2], a);
            a = fmaf(t.w, wv[k4 * 4 + 3], a);
        }
        acc[row] = a;
    }

    const int b  = row0 >> 11;
    const int n0 = row0 & (SEQ - 1);
    const int which = c >> 7;
    const int cc = c & 127;
    const int hh = cc >> 5, dd = cc & 31;
    const float qscale = 0.17677669529663687f * LOG2E;

    if (which < 2) {
        const int fslot = perm16(dd);
        __nv_bfloat16* dst = (which == 0) ? g_qa : g_ka;
        const float sc = (which == 0) ? qscale : 1.0f;
        size_t base = ((size_t)(b * HEADS + hh) * SEQ + n0) * FEAT + fslot;
        #pragma unroll
        for (int row = 0; row < ROWS2; row++)
            dst[base + (size_t)row * FEAT] = __float2bfloat16(acc[row] * sc);
    } else {
        // V^T: 32 consecutive n = two permuted 16-groups -> 4 uint4 stores
        size_t base = ((size_t)(b * HEADS + hh) * HD + dd) * SEQ + n0;
        #pragma unroll
        for (int gset = 0; gset < 2; gset++) {
            const float* a = acc + gset * 16;
            uint4 w0, w1;
            w0.x = packbf(a[0],  a[1]);  w0.y = packbf(a[8],  a[9]);
            w0.z = packbf(a[2],  a[3]);  w0.w = packbf(a[10], a[11]);
            w1.x = packbf(a[4],  a[5]);  w1.y = packbf(a[12], a[13]);
            w1.z = packbf(a[6],  a[7]);  w1.w = packbf(a[14], a[15]);
            *(uint4*)&g_vt[base + gset * 16 + 0] = w0;
            *(uint4*)&g_vt[base + gset * 16 + 8] = w1;
        }
    }
}

// =============================================================================
// Kernel B: tensor-core attention. QTILE=128, CHUNK=64, 256 threads.
// adj enters through the MMA accumulator init (C-operand does the add).
// =============================================================================
__global__ __launch_bounds__(256, 3) void attn_kernel()
{
    extern __shared__ __align__(16) char smem_raw[];

    const int tid  = threadIdx.x;
    const int lane = tid & 31;
    const int warp = tid >> 5;
    const int gid  = lane >> 2;
    const int tig  = lane & 3;
    const int h = blockIdx.y, b = blockIdx.z;
    const int q0 = blockIdx.x * QTILE;
    const int qrow = warp * 16;

    const size_t bh     = (size_t)(b * HEADS + h);
    const size_t krow0  = bh * SEQ;
    const size_t vtrow0 = bh * HD;

    const unsigned sbase = (unsigned)__cvta_generic_to_shared(smem_raw);

    unsigned qa[3][4];
    {
        const __nv_bfloat16* q0p = g_qa + (krow0 + q0 + qrow + gid) * FEAT;
        #pragma unroll
        for (int kk = 0; kk < 3; kk++) {
            uint2 t0 = *(const uint2*)(q0p + 16 * kk + 4 * tig);
            uint2 t1 = *(const uint2*)(q0p + 8 * FEAT + 16 * kk + 4 * tig);
            qa[kk][0] = t0.x; qa[kk][1] = t1.x; qa[kk][2] = t0.y; qa[kk][3] = t1.y;
        }
    }

    float o[4][4];
    #pragma unroll
    for (int i = 0; i < 4; i++)
        #pragma unroll
        for (int j = 0; j < 4; j++) o[i][j] = 0.f;
    float rs0 = 0.f, rs1 = 0.f;

    auto stage = [&](int jc, int s) {
        const int j0 = jc * CHUNK;
        const unsigned kd = sbase + s * STAGE_SZ + K_OFF;
        const unsigned vd = sbase + s * STAGE_SZ + V_OFF;
        const unsigned ad = sbase + s * STAGE_SZ + A_OFF;
        {   // K: 64 x 48 el = 384 uint4
            int e = tid, r = e / 6, c = e - r * 6;
            cp16(kd + (r * KPAD + c * 8) * 2, g_ka + (krow0 + j0 + r) * FEAT + c * 8);
            e = tid + 256;
            if (e < 384) {
                r = e / 6; c = e - r * 6;
                cp16(kd + (r * KPAD + c * 8) * 2, g_ka + (krow0 + j0 + r) * FEAT + c * 8);
            }
        }
        {   // V^T: 32 x 64 el = 256 uint4
            int r = tid >> 3, c = tid & 7;
            cp16(vd + (r * VPAD + c * 8) * 2, g_vt + (vtrow0 + r) * SEQ + j0 + c * 8);
        }
        #pragma unroll
        for (int i = 0; i < 4; i++) {   // adj: 128 x 64 el = 1024 uint4
            int e = tid + i * 256, r = e >> 3, c = e & 7;
            cp16(ad + (r * APAD + c * 8) * 2, g_adjb + (size_t)(q0 + r) * SEQ + j0 + c * 8);
        }
    };

    stage(0, 0);
    asm volatile("cp.async.commit_group;");

    for (int jc = 0; jc < NCH; jc++) {
        const int s = jc & 1;
        if (jc + 1 < NCH) {
            stage(jc + 1, s ^ 1);
            asm volatile("cp.async.commit_group;");
            asm volatile("cp.async.wait_group 1;");
        } else {
            asm volatile("cp.async.wait_group 0;");
        }
        __syncthreads();

        const __nv_bfloat16* Ks   = (const __nv_bfloat16*)(smem_raw + s * STAGE_SZ + K_OFF);
        const __nv_bfloat16* Vts  = (const __nv_bfloat16*)(smem_raw + s * STAGE_SZ + V_OFF);
        const __nv_bfloat16* Adjs = (const __nv_bfloat16*)(smem_raw + s * STAGE_SZ + A_OFF);

        #pragma unroll
        for (int gl = 0; gl < 4; gl++) {       // 16 keys per gl, 64 total
            unsigned pa[4];
            #pragma unroll
            for (int t = 0; t < 2; t++) {
                const int kr = gl * 16 + t * 8;
                // adj first -> MMA accumulator init (C-operand adds for free)
                unsigned au0 = *(const unsigned*)&Adjs[(qrow + gid) * APAD + kr + 2 * tig];
                unsigned au1 = *(const unsigned*)&Adjs[(qrow + gid + 8) * APAD + kr + 2 * tig];
                float c0 = bflo(au0), c1 = bfhi(au0);
                float c2 = bflo(au1), c3 = bfhi(au1);
                #pragma unroll
                for (int kk = 0; kk < 3; kk++) {
                    uint2 bb = *(const uint2*)&Ks[(kr + gid) * KPAD + 16 * kk + 4 * tig];
                    mma16816(c0, c1, c2, c3,
                             qa[kk][0], qa[kk][1], qa[kk][2], qa[kk][3], bb.x, bb.y);
                }
                c0 = ex2f(c0);
                c1 = ex2f(c1);
                c2 = ex2f(c2);
                c3 = ex2f(c3);
                rs0 += c0 + c1;
                rs1 += c2 + c3;
                pa[2 * t]     = packbf(c0, c1);
                pa[2 * t + 1] = packbf(c2, c3);
            }
            #pragma unroll
            for (int nf = 0; nf < 4; nf++) {
                uint2 bb = *(const uint2*)&Vts[(8 * nf + gid) * VPAD + 16 * gl + 4 * tig];
                mma16816(o[nf][0], o[nf][1], o[nf][2], o[nf][3],
                         pa[0], pa[1], pa[2], pa[3], bb.x, bb.y);
            }
        }
        __syncthreads();
    }

    rs0 += __shfl_xor_sync(0xffffffffu, rs0, 1);
    rs0 += __shfl_xor_sync(0xffffffffu, rs0, 2);
    rs1 += __shfl_xor_sync(0xffffffffu, rs1, 1);
    rs1 += __shfl_xor_sync(0xffffffffu, rs1, 2);
    const float i0 = 1.f / rs0, i1 = 1.f / rs1;

    const size_t orow = bh * SEQ + q0 + qrow + gid;
    #pragma unroll
    for (int nf = 0; nf < 4; nf++) {
        *(float2*)&g_o[orow * HD + 8 * nf + 2 * tig] =
            make_float2(o[nf][0] * i0, o[nf][1] * i0);
        *(float2*)&g_o[(orow + 8) * HD + 8 * nf + 2 * tig] =
            make_float2(o[nf][2] * i1, o[nf][3] * i1);
    }
}

// =============================================================================
// Kernel C: warp-per-row output projection + residual + LayerNorm + reg tail.
// =============================================================================
__global__ __launch_bounds__(256) void epi_kernel(
    const float* __restrict__ x, const float* __restrict__ Wol,
    const float* __restrict__ bol, const float* __restrict__ Woh,
    const float* __restrict__ boh, const float* __restrict__ gamma,
    const float* __restrict__ beta, const float* __restrict__ log_reg_w,
    float* __restrict__ out, int out_size)
{
    const int warp = threadIdx.x >> 5;
    const int lane = threadIdx.x & 31;
    const int row  = blockIdx.x * 8 + warp;
    const int b    = row >> 11;
    const int n    = row & (SEQ - 1);

    float ov[4];
    #pragma unroll
    for (int i = 0; i < 4; i++)
        ov[i] = g_o[(((size_t)(b * HEADS + i)) * SEQ + n) * HD + lane];

    float t8[8];
    #pragma unroll
    for (int r = 0; r < 8; r++) t8[r] = 0.f;
    #pragma unroll
    for (int i = 0; i < 4; i++) {
        const int d = lane + 32 * i;
        const float4* wp = (const float4*)(Wol + d * RNK);
        float4 w0 = wp[0], w1 = wp[1];
        t8[0] = fmaf(ov[i], w0.x, t8[0]);
        t8[1] = fmaf(ov[i], w0.y, t8[1]);
        t8[2] = fmaf(ov[i], w0.z, t8[2]);
        t8[3] = fmaf(ov[i], w0.w, t8[3]);
        t8[4] = fmaf(ov[i], w1.x, t8[4]);
        t8[5] = fmaf(ov[i], w1.y, t8[5]);
        t8[6] = fmaf(ov[i], w1.z, t8[6]);
        t8[7] = fmaf(ov[i], w1.w, t8[7]);
    }
    #pragma unroll
    for (int r = 0; r < 8; r++) {
        #pragma unroll
        for (int off = 16; off > 0; off >>= 1)
            t8[r] += __shfl_xor_sync(0xffffffffu, t8[r], off);
        t8[r] += bol[r];
    }

    float y[4];
    #pragma unroll
    for (int i = 0; i < 4; i++) {
        const int d = lane + 32 * i;
        float o2 = boh[d];
        #pragma unroll
        for (int r = 0; r < 8; r++) o2 = fmaf(t8[r], Woh[r * HDIM + d], o2);
        y[i] = o2 + x[(size_t)row * HDIM + d];
    }

    float s = y[0] + y[1] + y[2] + y[3];
    #pragma unroll
    for (int off = 16; off > 0; off >>= 1)
        s += __shfl_xor_sync(0xffffffffu, s, off);
    const float mu = s * (1.0f / HDIM);

    float v = 0.f;
    #pragma unroll
    for (int i = 0; i < 4; i++) { y[i] -= mu; v = fmaf(y[i], y[i], v); }
    #pragma unroll
    for (int off = 16; off > 0; off >>= 1)
        v += __shfl_xor_sync(0xffffffffu, v, off);
    const float rstd = rsqrtf(v * (1.0f / HDIM) + 1e-5f);

    #pragma unroll
    for (int i = 0; i < 4; i++) {
        const int d = lane + 32 * i;
        out[(size_t)row * HDIM + d] = y[i] * rstd * gamma[d] + beta[d];
    }

    if (row == 0 && lane == 0) {
        float reg = expf(log_reg_w[0]) * (1.0f / (float)SEQ);
        for (int i = NTOT; i < out_size; i++) out[i] = reg;
    }
}

// =============================================================================
extern "C" void kernel_launch(void* const* d_in, const int* in_sizes, int n_in,
                              void* d_out, int out_size)
{
    const float* x         = (const float*)d_in[0];
    const float* Wql       = (const float*)d_in[1];
    const float* bql       = (const float*)d_in[2];
    const float* Wqh       = (const float*)d_in[3];
    const float* bqh       = (const float*)d_in[4];
    const float* u         = (const float*)d_in[5];
    const float* v         = (const float*)d_in[6];
    const float* adj_scale = (const float*)d_in[7];
    const float* Wol       = (const float*)d_in[8];
    const float* bol       = (const float*)d_in[9];
    const float* Woh       = (const float*)d_in[10];
    const float* boh       = (const float*)d_in[11];
    const float* gamma     = (const float*)d_in[12];
    const float* beta      = (const float*)d_in[13];
    const float* log_reg_w = (const float*)d_in[14];
    const float* adj_prior = (const float*)d_in[15];
    float* out = (float*)d_out;

    static bool attr_set = false;
    if (!attr_set) {
        cudaFuncSetAttribute(attn_kernel,
                             cudaFuncAttributeMaxDynamicSharedMemorySize, ATTN_SMEM);
        attr_set = true;
    }

    adjcvt_kernel<<<(SEQ * SEQ) / (8 * 256), 256>>>(adj_prior, adj_scale);
    aug_kernel<<<(HEADS * SEQ + 255) / 256, 256>>>(u, v);
    qkv1_kernel<<<(BATCH * SEQ) / 64, 256>>>(x, Wql, bql);
    qkv2_kernel<<<(BATCH * SEQ) / ROWS2, 384>>>(Wqh, bqh);
    attn_kernel<<<dim3(SEQ / QTILE, HEADS, BATCH), 256, ATTN_SMEM>>>();
    epi_kernel<<<(BATCH * SEQ) / 8, 256>>>(x, Wol, bol, Woh, boh, gamma, beta,
                                           log_reg_w, out, out_size);
}